// round 3
// baseline (speedup 1.0000x reference)
#include <cuda_runtime.h>
#include <cstdint>

typedef unsigned long long u64;
typedef unsigned int u32;

#define BMAX 8
#define NPROP 4000
#define NCLS 91
#define NC1 90
#define CAP 81920
#define SHCAP 16384
#define KPRE 2048
#define SCORE_TH 0.05f
#define NMS_TH 0.5f
#define XFORM_CLIP 4.135166556742356f
#define DETS 100

__device__ int g_cnt[BMAX];   // zero-initialized at load; reset at end of k_main
__device__ u64 g_keys[BMAX][CAP];

__device__ __forceinline__ float read_dim(const void* p) {
    int v = *(const int*)p;
    if (v > 0 && v < 1000000) return (float)v;
    return *(const float*)p;
}

// FMA-pipe exp (avoids MUFU.EX2 throughput floor). rel err ~2e-6.
__device__ __forceinline__ float fexp(float x) {
    float t = x * 1.4426950408889634f;
    t = fmaxf(t, -126.0f);
    float k = rintf(t);
    float f = t - k;
    float p = 1.3333558146e-3f;
    p = fmaf(p, f, 9.6181291077e-3f);
    p = fmaf(p, f, 5.5504108664e-2f);
    p = fmaf(p, f, 2.4022650695e-1f);
    p = fmaf(p, f, 6.9314718056e-1f);
    p = fmaf(p, f, 1.0f);
    float s = __int_as_float(((int)k + 127) << 23);
    return p * s;
}

// One warp per proposal row: softmax over 91 logits, threshold, validity check,
// emit 64-bit sortable key (inverted score bits | flat index).
__global__ void k_cand(const float* __restrict__ logits,
                       const float* __restrict__ reg,
                       const float* __restrict__ props,
                       const void* __restrict__ p_h,
                       const void* __restrict__ p_w,
                       int B) {
    int wid = threadIdx.x >> 5, lane = threadIdx.x & 31;
    int row = blockIdx.x * 8 + wid;
    if (row >= B * NPROP) return;
    int b = row / NPROP;
    int n = row - b * NPROP;

    const float* lr = logits + (size_t)row * NCLS;
    float l0 = lr[lane];
    float l1 = lr[lane + 32];
    float l2 = (lane < NCLS - 64) ? lr[lane + 64] : -3.0e38f;

    float m = fmaxf(fmaxf(l0, l1), l2);
    #pragma unroll
    for (int o = 16; o; o >>= 1) m = fmaxf(m, __shfl_xor_sync(~0u, m, o));

    float e0 = fexp(l0 - m);
    float e1 = fexp(l1 - m);
    float e2 = (lane < NCLS - 64) ? fexp(l2 - m) : 0.0f;
    float sum = e0 + e1 + e2;
    #pragma unroll
    for (int o = 16; o; o >>= 1) sum += __shfl_xor_sync(~0u, sum, o);
    float inv = 1.0f / sum;

    float img_h = read_dim(p_h);
    float img_w = read_dim(p_w);

    float4 pr = *(const float4*)(props + (size_t)row * 4);
    float pwd = pr.z - pr.x, pht = pr.w - pr.y;
    float cx = pr.x + 0.5f * pwd, cy = pr.y + 0.5f * pht;

    #pragma unroll
    for (int slot = 0; slot < 3; slot++) {
        int p = lane + 32 * slot;
        if (p < 1 || p >= NCLS) continue;
        float e = (slot == 0) ? e0 : (slot == 1 ? e1 : e2);
        float s = e * inv;
        if (s > SCORE_TH) {
            float4 rg = *(const float4*)(reg + (size_t)row * 4 * NCLS + 4 * p);
            float dx = rg.x / 10.0f, dy = rg.y / 10.0f;
            float dw = fminf(rg.z / 5.0f, XFORM_CLIP);
            float dh = fminf(rg.w / 5.0f, XFORM_CLIP);
            float pcx = dx * pwd + cx, pcy = dy * pht + cy;
            float bw = expf(dw) * pwd, bh = expf(dh) * pht;
            float x1 = fminf(fmaxf(pcx - 0.5f * bw, 0.0f), img_w);
            float y1 = fminf(fmaxf(pcy - 0.5f * bh, 0.0f), img_h);
            float x2 = fminf(fmaxf(pcx + 0.5f * bw, 0.0f), img_w);
            float y2 = fminf(fmaxf(pcy + 0.5f * bh, 0.0f), img_h);
            if ((x2 - x1 >= 1.0f) && (y2 - y1 >= 1.0f)) {
                u32 sb = __float_as_uint(s);
                u32 mf = (u32)(n * NC1 + (p - 1));
                u64 key = ((u64)(sb ^ 0xFFFFFFFFu) << 32) | (u64)mf;
                int idx = atomicAdd(&g_cnt[b], 1);
                if (idx < CAP) g_keys[b][idx] = key;
            }
        }
    }
}

// dynamic smem: phase 1 = key staging (128KB); phase 2 aliased box arrays.
extern __shared__ __align__(16) unsigned char dynbuf[];
#define DYN_BYTES 131072

__device__ __forceinline__ float iou_sup(float4 bi, float ai, float4 bj, float aj) {
    float w = fminf(bi.z, bj.z) - fmaxf(bi.x, bj.x);
    float h = fminf(bi.w, bj.w) - fmaxf(bi.y, bj.y);
    w = fmaxf(w, 0.0f); h = fmaxf(h, 0.0f);
    float inter = w * h;
    return (inter > NMS_TH * (ai + aj - inter)) ? 1.0f : 0.0f;
}

// One block (1024 thr) per image: radix-select rank-2048, register bitonic
// sort, fused decode, fused word-sequential NMS (on-the-fly IoU), output.
__global__ void __launch_bounds__(1024, 1)
k_main(const float* __restrict__ reg,
       const float* __restrict__ props,
       const void* __restrict__ p_h,
       const void* __restrict__ p_w,
       float* __restrict__ out, int B) {
    int b = blockIdx.x;
    int tid = threadIdx.x, lane = tid & 31, wid = tid >> 5;
    const int T = 1024;

    __shared__ u64 sh_list[KPRE];          // 16KB
    __shared__ int sh_hist[256];
    __shared__ int sh_pref[256];
    __shared__ u64 sh_prefix;
    __shared__ int sh_rem;
    __shared__ int sh_c2;
    __shared__ float sh_red[32];
    __shared__ u64 sh_sup[32], sh_valid[32], sh_kept[32];
    __shared__ u64 sh_m[64];
    __shared__ u64 sh_cur;
    __shared__ u32 sh_b0, sh_b1;
    __shared__ int sh_idx[64];
    __shared__ int sh_nk;

    u64* keys_sh = (u64*)dynbuf;
    float4* s_obox = (float4*)dynbuf;                 // 32KB
    float4* s_box = (float4*)(dynbuf + 32768);        // 32KB
    float* s_area = (float*)(dynbuf + 65536);         // 8KB
    float* s_score = (float*)(dynbuf + 73728);        // 8KB
    int* s_label = (int*)(dynbuf + 81920);            // 8KB

    int cnt = g_cnt[b];
    if (cnt > CAP) cnt = CAP;
    bool use_sh = (cnt <= SHCAP);
    const u64* keys = use_sh ? (const u64*)keys_sh : (const u64*)g_keys[b];
    if (use_sh) {
        for (int i = tid; i < cnt; i += T) keys_sh[i] = g_keys[b][i];
    }
    __syncthreads();

    // ---- radix-select rank-KPRE threshold ----
    u64 thresh = ~0ull;
    if (cnt > KPRE) {
        if (tid == 0) { sh_prefix = 0ull; sh_rem = KPRE; }
        __syncthreads();
        for (int shift = 56; shift >= 0; shift -= 8) {
            if (tid < 256) sh_hist[tid] = 0;
            __syncthreads();
            u64 prefix = sh_prefix;
            u64 hm = (shift == 56) ? 0ull : (~0ull << (shift + 8));
            for (int i = tid; i < cnt; i += T) {
                u64 k = keys[i];
                if ((k & hm) == prefix)
                    atomicAdd(&sh_hist[(int)((k >> shift) & 0xFF)], 1);
            }
            __syncthreads();
            if (tid < 256) sh_pref[tid] = sh_hist[tid];
            __syncthreads();
            for (int o = 1; o < 256; o <<= 1) {
                int v = 0;
                if (tid < 256 && tid >= o) v = sh_pref[tid - o];
                __syncthreads();
                if (tid < 256 && tid >= o) sh_pref[tid] += v;
                __syncthreads();
            }
            int rem = sh_rem;
            int excl = 0, incl = 0;
            if (tid < 256) { incl = sh_pref[tid]; excl = incl - sh_hist[tid]; }
            __syncthreads();
            if (tid < 256 && excl < rem && rem <= incl) {
                sh_prefix = prefix | ((u64)tid << shift);
                sh_rem = rem - excl;
            }
            __syncthreads();
        }
        thresh = sh_prefix;
    }

    // ---- collect ----
    if (tid == 0) sh_c2 = 0;
    __syncthreads();
    for (int i = tid; i < cnt; i += T) {
        u64 k = keys[i];
        if (k <= thresh) {
            int pos = atomicAdd(&sh_c2, 1);
            if (pos < KPRE) sh_list[pos] = k;
        }
    }
    __syncthreads();
    int got = sh_c2; if (got > KPRE) got = KPRE;
    for (int t = got + tid; t < KPRE; t += T) sh_list[t] = ~0ull;
    __syncthreads();

    // ---- register bitonic sort: 2 elems/thread ----
    {
        u64 v0 = sh_list[tid], v1 = sh_list[tid + 1024];
        const int i0 = tid, i1 = tid + 1024;
        for (int size = 2; size <= KPRE; size <<= 1) {
            for (int stride = size >> 1; stride > 0; stride >>= 1) {
                if (stride == 1024) {
                    u64 a = v0 < v1 ? v0 : v1;
                    u64 c = v0 < v1 ? v1 : v0;
                    v0 = a; v1 = c;
                } else if (stride >= 32) {
                    sh_list[i0] = v0; sh_list[i1] = v1;
                    __syncthreads();
                    u64 p0 = sh_list[i0 ^ stride];
                    u64 p1 = sh_list[i1 ^ stride];
                    bool tm0 = ((i0 & size) == 0) ^ ((i0 & stride) != 0);
                    bool tm1 = ((i1 & size) == 0) ^ ((i1 & stride) != 0);
                    v0 = tm0 ? (v0 < p0 ? v0 : p0) : (v0 < p0 ? p0 : v0);
                    v1 = tm1 ? (v1 < p1 ? v1 : p1) : (v1 < p1 ? p1 : v1);
                    __syncthreads();
                } else {
                    u64 p0 = __shfl_xor_sync(~0u, v0, stride);
                    u64 p1 = __shfl_xor_sync(~0u, v1, stride);
                    bool tm0 = ((i0 & size) == 0) ^ ((i0 & stride) != 0);
                    bool tm1 = ((i1 & size) == 0) ^ ((i1 & stride) != 0);
                    v0 = tm0 ? (v0 < p0 ? v0 : p0) : (v0 < p0 ? p0 : v0);
                    v1 = tm1 ? (v1 < p1 ? v1 : p1) : (v1 < p1 ? p1 : v1);
                }
            }
        }
        sh_list[i0] = v0; sh_list[i1] = v1;
        __syncthreads();
    }

    // ---- fused decode into smem (aliases key buffer; keys fully consumed) ----
    float img_h = read_dim(p_h);
    float img_w = read_dim(p_w);
    float lmax = 0.0f;
    for (int s = tid; s < KPRE; s += T) {
        u64 k = sh_list[s];
        float4 bx = make_float4(0.f, 0.f, 0.f, 0.f);
        float sc = -1.0f;
        int lab = 0;
        if (k != ~0ull) {
            u32 mf = (u32)(k & 0xFFFFFFFFu);
            sc = __uint_as_float(~((u32)(k >> 32)));
            int n = (int)(mf / NC1);
            int p = (int)(mf - (u32)n * NC1) + 1;
            int row = b * NPROP + n;
            float4 pr = *(const float4*)(props + (size_t)row * 4);
            float pwd = pr.z - pr.x, pht = pr.w - pr.y;
            float cx = pr.x + 0.5f * pwd, cy = pr.y + 0.5f * pht;
            float4 rg = *(const float4*)(reg + (size_t)row * 4 * NCLS + 4 * p);
            float dx = rg.x / 10.0f, dy = rg.y / 10.0f;
            float dw = fminf(rg.z / 5.0f, XFORM_CLIP);
            float dh = fminf(rg.w / 5.0f, XFORM_CLIP);
            float pcx = dx * pwd + cx, pcy = dy * pht + cy;
            float bw = expf(dw) * pwd, bh = expf(dh) * pht;
            bx.x = fminf(fmaxf(pcx - 0.5f * bw, 0.0f), img_w);
            bx.y = fminf(fmaxf(pcy - 0.5f * bh, 0.0f), img_h);
            bx.z = fminf(fmaxf(pcx + 0.5f * bw, 0.0f), img_w);
            bx.w = fminf(fmaxf(pcy + 0.5f * bh, 0.0f), img_h);
            lab = p;
            lmax = fmaxf(lmax, fmaxf(fmaxf(bx.x, bx.y), fmaxf(bx.z, bx.w)));
        }
        s_box[s] = bx;
        s_score[s] = sc;
        s_label[s] = lab;
    }
    #pragma unroll
    for (int o = 16; o; o >>= 1) lmax = fmaxf(lmax, __shfl_xor_sync(~0u, lmax, o));
    if (lane == 0) sh_red[wid] = lmax;
    __syncthreads();
    if (tid < 32) {
        float v = sh_red[tid];
        #pragma unroll
        for (int o = 16; o; o >>= 1) v = fmaxf(v, __shfl_xor_sync(~0u, v, o));
        if (tid == 0) sh_red[0] = v;
    }
    __syncthreads();
    float mc = sh_red[0];
    for (int s = tid; s < KPRE; s += T) {
        float4 bx = s_box[s];
        float off = (float)s_label[s] * (mc + 1.0f);
        float4 ob = make_float4(bx.x + off, bx.y + off, bx.z + off, bx.w + off);
        s_obox[s] = ob;
        s_area[s] = (ob.z - ob.x) * (ob.w - ob.y);
    }

    // valid mask (score > thresh), init sup/kept
    {
        int s0 = wid * 64 + lane;
        float sc0 = (tid < T) ? 0.f : 0.f;
        u32 v0 = 0, v1 = 0;
        __syncthreads();
        v0 = __ballot_sync(~0u, s_score[s0] > SCORE_TH);
        v1 = __ballot_sync(~0u, s_score[s0 + 32] > SCORE_TH);
        if (lane == 0) {
            sh_valid[wid] = ((u64)v1 << 32) | (u64)v0;
            sh_sup[wid] = 0ull;
            sh_kept[wid] = 0ull;
        }
        (void)sc0;
    }
    __syncthreads();

    // ---- word-sequential greedy NMS with on-the-fly IoU ----
    for (int w = 0; w < 32; w++) {
        __syncthreads();
        u64 kw = sh_valid[w] & ~sh_sup[w];
        if (kw == 0ull) continue;   // uniform

        // Phase A: intra-word 64x64 forward masks
        if (tid < 64) sh_m[tid] = 0ull;
        __syncthreads();
        {
            int i = tid >> 4, j0 = (tid & 15) * 4;
            float4 bi = s_obox[w * 64 + i];
            float ai = s_area[w * 64 + i];
            u64 bits = 0ull;
            #pragma unroll
            for (int dj = 0; dj < 4; dj++) {
                int j = j0 + dj;
                if (j > i) {
                    if (iou_sup(bi, ai, s_obox[w * 64 + j], s_area[w * 64 + j]) > 0.5f)
                        bits |= (1ull << j);
                }
            }
            if (bits) atomicOr(&sh_m[i], bits);
        }
        if (tid == 0) sh_cur = kw;
        __syncthreads();

        // Phase B: intra-word Jacobi -> greedy fixpoint
        u64 cur;
        for (;;) {
            cur = sh_cur;
            bool nb = false;
            if (tid < 64 && ((kw >> tid) & 1ull)) {
                u64 lower = cur & ((1ull << tid) - 1ull);
                bool sup = false;
                while (lower) {
                    int i = __ffsll((long long)lower) - 1;
                    lower &= lower - 1;
                    if ((sh_m[i] >> tid) & 1ull) { sup = true; break; }
                }
                nb = !sup;
            }
            u32 bal = __ballot_sync(~0u, nb);
            if (tid == 0) sh_b0 = bal;
            if (tid == 32) sh_b1 = bal;
            __syncthreads();
            u64 nk = ((u64)sh_b1 << 32) | (u64)sh_b0;
            if (nk == cur) break;
            if (tid == 0) sh_cur = nk;
            __syncthreads();
        }
        // gather kept indices of this word
        if (tid < 64 && ((cur >> tid) & 1ull)) {
            int pos = __popcll(cur & ((1ull << tid) - 1ull));
            sh_idx[pos] = w * 64 + tid;
        }
        if (tid == 0) { sh_nk = __popcll(cur); sh_kept[w] = cur; }
        __syncthreads();

        // Phase C: kept boxes of word w suppress later columns
        int nk = sh_nk;
        for (int j = (w + 1) * 64 + tid; j < KPRE; j += T) {
            float4 bj = s_obox[j];
            float aj = s_area[j];
            bool s = false;
            for (int k = 0; k < nk; k++) {
                int i = sh_idx[k];
                if (iou_sup(s_obox[i], s_area[i], bj, aj) > 0.5f) { s = true; break; }
            }
            u32 bal = __ballot_sync(~0u, s);
            if (lane == 0 && bal) {
                int base = j;  // lane 0's j, 32-aligned
                atomicOr(&sh_sup[base >> 6], ((u64)bal) << (base & 63));
            }
        }
    }
    __syncthreads();

    // ---- output: defaults then first 100 kept in sorted order ----
    const int soff = B * DETS * 4;
    const int loff = B * DETS * 4 + B * DETS;
    for (int i = tid; i < DETS; i += T) {
        float* bo = out + (size_t)(b * DETS + i) * 4;
        bo[0] = 0.f; bo[1] = 0.f; bo[2] = 0.f; bo[3] = 0.f;
        out[soff + b * DETS + i] = 0.f;
        out[loff + b * DETS + i] = -1.f;
    }
    __syncthreads();

    if (wid == 0) {
        int base = 0;
        for (int w = 0; w < 32 && base < DETS; w++) {
            u64 word = sh_kept[w];
            u32 lo = (u32)word;
            u32 hi = (u32)(word >> 32);
            {
                u32 myb = (lo >> lane) & 1u;
                int pre = __popc(lo & ((1u << lane) - 1u));
                int rank = base + pre;
                if (myb && rank < DETS) {
                    int s = w * 64 + lane;
                    float4 bx = s_box[s];
                    float* bo = out + (size_t)(b * DETS + rank) * 4;
                    bo[0] = bx.x; bo[1] = bx.y; bo[2] = bx.z; bo[3] = bx.w;
                    out[soff + b * DETS + rank] = s_score[s];
                    out[loff + b * DETS + rank] = (float)s_label[s];
                }
                base += __popc(lo);
            }
            {
                u32 myb = (hi >> lane) & 1u;
                int pre = __popc(hi & ((1u << lane) - 1u));
                int rank = base + pre;
                if (myb && rank < DETS) {
                    int s = w * 64 + 32 + lane;
                    float4 bx = s_box[s];
                    float* bo = out + (size_t)(b * DETS + rank) * 4;
                    bo[0] = bx.x; bo[1] = bx.y; bo[2] = bx.z; bo[3] = bx.w;
                    out[soff + b * DETS + rank] = s_score[s];
                    out[loff + b * DETS + rank] = (float)s_label[s];
                }
                base += __popc(hi);
            }
        }
    }
    if (tid == 0) g_cnt[b] = 0;   // reset for next call
}

extern "C" void kernel_launch(void* const* d_in, const int* in_sizes, int n_in,
                              void* d_out, int out_size) {
    const float* logits = (const float*)d_in[0];
    const float* reg = (const float*)d_in[1];
    const float* props = (const float*)d_in[2];
    const void* p_h = d_in[3];
    const void* p_w = d_in[4];
    float* out = (float*)d_out;

    int B = in_sizes[0] / (NPROP * NCLS);
    if (B < 1) B = 1;
    if (B > BMAX) B = BMAX;

    cudaFuncSetAttribute(k_main, cudaFuncAttributeMaxDynamicSharedMemorySize,
                         DYN_BYTES);

    int rows = B * NPROP;
    k_cand<<<(rows + 7) / 8, 256>>>(logits, reg, props, p_h, p_w, B);
    k_main<<<B, 1024, DYN_BYTES>>>(reg, props, p_h, p_w, out, B);
}

// round 5
// speedup vs baseline: 5.2414x; 5.2414x over previous
#include <cuda_runtime.h>
#include <cstdint>

typedef unsigned long long u64;
typedef unsigned int u32;

#define BMAX 8
#define NPROP 4000
#define NCLS 91
#define NC1 90
#define CAP 81920
#define SHCAP 16384
#define KPRE 2048
#define SCORE_TH 0.05f
#define NMS_TH 0.5f
#define XFORM_CLIP 4.135166556742356f
#define DETS 100
#define EDGE_CAP 8192

__device__ int g_cnt[BMAX];   // zero-init at load; reset at end of k_main
__device__ u64 g_keys[BMAX][CAP];

__device__ __forceinline__ float read_dim(const void* p) {
    int v = *(const int*)p;
    if (v > 0 && v < 1000000) return (float)v;
    return *(const float*)p;
}

// FMA-pipe exp (avoids MUFU.EX2 throughput floor). rel err ~2e-6.
__device__ __forceinline__ float fexp(float x) {
    float t = x * 1.4426950408889634f;
    t = fmaxf(t, -126.0f);
    float k = rintf(t);
    float f = t - k;
    float p = 1.3333558146e-3f;
    p = fmaf(p, f, 9.6181291077e-3f);
    p = fmaf(p, f, 5.5504108664e-2f);
    p = fmaf(p, f, 2.4022650695e-1f);
    p = fmaf(p, f, 6.9314718056e-1f);
    p = fmaf(p, f, 1.0f);
    float s = __int_as_float(((int)k + 127) << 23);
    return p * s;
}

// One warp per proposal row: softmax over 91 logits, threshold, validity check,
// emit 64-bit sortable key (inverted score bits | flat index).
__global__ void k_cand(const float* __restrict__ logits,
                       const float* __restrict__ reg,
                       const float* __restrict__ props,
                       const void* __restrict__ p_h,
                       const void* __restrict__ p_w,
                       int B) {
    int wid = threadIdx.x >> 5, lane = threadIdx.x & 31;
    int row = blockIdx.x * 8 + wid;
    if (row >= B * NPROP) return;
    int b = row / NPROP;
    int n = row - b * NPROP;

    const float* lr = logits + (size_t)row * NCLS;
    float l0 = lr[lane];
    float l1 = lr[lane + 32];
    float l2 = (lane < NCLS - 64) ? lr[lane + 64] : -3.0e38f;

    float m = fmaxf(fmaxf(l0, l1), l2);
    #pragma unroll
    for (int o = 16; o; o >>= 1) m = fmaxf(m, __shfl_xor_sync(~0u, m, o));

    float e0 = fexp(l0 - m);
    float e1 = fexp(l1 - m);
    float e2 = (lane < NCLS - 64) ? fexp(l2 - m) : 0.0f;
    float sum = e0 + e1 + e2;
    #pragma unroll
    for (int o = 16; o; o >>= 1) sum += __shfl_xor_sync(~0u, sum, o);
    float inv = 1.0f / sum;

    float img_h = read_dim(p_h);
    float img_w = read_dim(p_w);

    float4 pr = *(const float4*)(props + (size_t)row * 4);
    float pwd = pr.z - pr.x, pht = pr.w - pr.y;
    float cx = pr.x + 0.5f * pwd, cy = pr.y + 0.5f * pht;

    #pragma unroll
    for (int slot = 0; slot < 3; slot++) {
        int p = lane + 32 * slot;
        if (p < 1 || p >= NCLS) continue;
        float e = (slot == 0) ? e0 : (slot == 1 ? e1 : e2);
        float s = e * inv;
        if (s > SCORE_TH) {
            float4 rg = *(const float4*)(reg + (size_t)row * 4 * NCLS + 4 * p);
            float dx = rg.x / 10.0f, dy = rg.y / 10.0f;
            float dw = fminf(rg.z / 5.0f, XFORM_CLIP);
            float dh = fminf(rg.w / 5.0f, XFORM_CLIP);
            float pcx = dx * pwd + cx, pcy = dy * pht + cy;
            float bw = expf(dw) * pwd, bh = expf(dh) * pht;
            float x1 = fminf(fmaxf(pcx - 0.5f * bw, 0.0f), img_w);
            float y1 = fminf(fmaxf(pcy - 0.5f * bh, 0.0f), img_h);
            float x2 = fminf(fmaxf(pcx + 0.5f * bw, 0.0f), img_w);
            float y2 = fminf(fmaxf(pcy + 0.5f * bh, 0.0f), img_h);
            if ((x2 - x1 >= 1.0f) && (y2 - y1 >= 1.0f)) {
                u32 sb = __float_as_uint(s);
                u32 mf = (u32)(n * NC1 + (p - 1));
                u64 key = ((u64)(sb ^ 0xFFFFFFFFu) << 32) | (u64)mf;
                int idx = atomicAdd(&g_cnt[b], 1);
                if (idx < CAP) g_keys[b][idx] = key;
            }
        }
    }
}

// dynamic smem: phase 1 = key staging (128KB); phase 2 aliased arrays.
extern __shared__ __align__(16) unsigned char dynbuf[];
#define DYN_BYTES 131072

// One block (1024 thr) per image: radix-select rank-2048 (early exit),
// register bitonic sort, fused decode, class-grouped sparse-edge NMS, output.
__global__ void __launch_bounds__(1024, 1)
k_main(const float* __restrict__ reg,
       const float* __restrict__ props,
       const void* __restrict__ p_h,
       const void* __restrict__ p_w,
       float* __restrict__ out, int B) {
    int b = blockIdx.x;
    int tid = threadIdx.x, lane = tid & 31, wid = tid >> 5;
    const int T = 1024;

    __shared__ u64 sh_list[KPRE];          // 16KB
    __shared__ int sh_hist[256];
    __shared__ int sh_pref[256];
    __shared__ u64 sh_prefix;
    __shared__ int sh_rem, sh_cbin;
    __shared__ int sh_c2;
    __shared__ float sh_red[32];
    __shared__ u64 sh_valid[32], sh_kept[32], sh_sup[32];
    __shared__ int sh_ccnt[92], sh_cbase[92];
    __shared__ int sh_ne, sh_changed;

    u64* keys_sh = (u64*)dynbuf;                      // phase 1 only
    float4* s_obox = (float4*)dynbuf;                 // 32KB
    float4* s_box  = (float4*)(dynbuf + 32768);       // 32KB
    float*  s_area = (float*)(dynbuf + 65536);        // 8KB
    float*  s_score= (float*)(dynbuf + 73728);        // 8KB
    int*    s_label= (int*)(dynbuf + 81920);          // 8KB
    int*    cls_idx= (int*)(dynbuf + 90112);          // 8KB
    u32*    edges  = (u32*)(dynbuf + 98304);          // 32KB -> 8192 edges

    int cnt = g_cnt[b];
    if (cnt > CAP) cnt = CAP;
    bool use_sh = (cnt <= SHCAP);
    const u64* keys = use_sh ? (const u64*)keys_sh : (const u64*)g_keys[b];
    if (use_sh) {
        for (int i = tid; i < cnt; i += T) keys_sh[i] = g_keys[b][i];
    }
    __syncthreads();

    // ---- radix-select rank-KPRE threshold (with whole-bin early exit) ----
    u64 thresh = ~0ull;
    if (cnt > KPRE) {
        if (tid == 0) { sh_prefix = 0ull; sh_rem = KPRE; sh_cbin = -1; }
        __syncthreads();
        for (int shift = 56; shift >= 0; shift -= 8) {
            if (tid < 256) sh_hist[tid] = 0;
            __syncthreads();
            u64 prefix = sh_prefix;
            u64 hm = (shift == 56) ? 0ull : (~0ull << (shift + 8));
            for (int i = tid; i < cnt; i += T) {
                u64 k = keys[i];
                if ((k & hm) == prefix)
                    atomicAdd(&sh_hist[(int)((k >> shift) & 0xFF)], 1);
            }
            __syncthreads();
            if (tid < 256) sh_pref[tid] = sh_hist[tid];
            __syncthreads();
            for (int o = 1; o < 256; o <<= 1) {
                int v = 0;
                if (tid < 256 && tid >= o) v = sh_pref[tid - o];
                __syncthreads();
                if (tid < 256 && tid >= o) sh_pref[tid] += v;
                __syncthreads();
            }
            int rem = sh_rem;
            int excl = 0, incl = 0;
            if (tid < 256) { incl = sh_pref[tid]; excl = incl - sh_hist[tid]; }
            __syncthreads();
            if (tid < 256 && excl < rem && rem <= incl) {
                sh_prefix = prefix | ((u64)tid << shift);
                sh_rem = rem - excl;
                sh_cbin = sh_hist[tid];
            }
            __syncthreads();
            // whole-bin early exit: remaining rank covers the full bin.
            if (sh_rem == sh_cbin) {
                if (tid == 0) {
                    u64 lowm = (shift == 0) ? 0ull : ((1ull << shift) - 1ull);
                    sh_prefix |= lowm;
                }
                __syncthreads();
                break;
            }
        }
        thresh = sh_prefix;
    }

    // ---- collect ----
    if (tid == 0) sh_c2 = 0;
    __syncthreads();
    for (int i = tid; i < cnt; i += T) {
        u64 k = keys[i];
        if (k <= thresh) {
            int pos = atomicAdd(&sh_c2, 1);
            if (pos < KPRE) sh_list[pos] = k;
        }
    }
    __syncthreads();
    int got = sh_c2; if (got > KPRE) got = KPRE;
    for (int t = got + tid; t < KPRE; t += T) sh_list[t] = ~0ull;
    __syncthreads();

    // ---- register bitonic sort: 2 elems/thread ----
    {
        u64 v0 = sh_list[tid], v1 = sh_list[tid + 1024];
        const int i0 = tid, i1 = tid + 1024;
        for (int size = 2; size <= KPRE; size <<= 1) {
            for (int stride = size >> 1; stride > 0; stride >>= 1) {
                if (stride == 1024) {
                    u64 a = v0 < v1 ? v0 : v1;
                    u64 c = v0 < v1 ? v1 : v0;
                    v0 = a; v1 = c;
                } else if (stride >= 32) {
                    sh_list[i0] = v0; sh_list[i1] = v1;
                    __syncthreads();
                    u64 p0 = sh_list[i0 ^ stride];
                    u64 p1 = sh_list[i1 ^ stride];
                    bool tm0 = ((i0 & size) == 0) ^ ((i0 & stride) != 0);
                    bool tm1 = ((i1 & size) == 0) ^ ((i1 & stride) != 0);
                    v0 = tm0 ? (v0 < p0 ? v0 : p0) : (v0 < p0 ? p0 : v0);
                    v1 = tm1 ? (v1 < p1 ? v1 : p1) : (v1 < p1 ? p1 : v1);
                    __syncthreads();
                } else {
                    u64 p0 = __shfl_xor_sync(~0u, v0, stride);
                    u64 p1 = __shfl_xor_sync(~0u, v1, stride);
                    bool tm0 = ((i0 & size) == 0) ^ ((i0 & stride) != 0);
                    bool tm1 = ((i1 & size) == 0) ^ ((i1 & stride) != 0);
                    v0 = tm0 ? (v0 < p0 ? v0 : p0) : (v0 < p0 ? p0 : v0);
                    v1 = tm1 ? (v1 < p1 ? v1 : p1) : (v1 < p1 ? p1 : v1);
                }
            }
        }
        sh_list[i0] = v0; sh_list[i1] = v1;
        __syncthreads();
    }

    // ---- fused decode into smem (aliases key buffer; keys fully consumed) ----
    float img_h = read_dim(p_h);
    float img_w = read_dim(p_w);
    float lmax = 0.0f;
    for (int s = tid; s < KPRE; s += T) {
        u64 k = sh_list[s];
        float4 bx = make_float4(0.f, 0.f, 0.f, 0.f);
        float sc = -1.0f;
        int lab = 0;
        if (k != ~0ull) {
            u32 mf = (u32)(k & 0xFFFFFFFFu);
            sc = __uint_as_float(~((u32)(k >> 32)));
            int n = (int)(mf / NC1);
            int p = (int)(mf - (u32)n * NC1) + 1;
            int row = b * NPROP + n;
            float4 pr = *(const float4*)(props + (size_t)row * 4);
            float pwd = pr.z - pr.x, pht = pr.w - pr.y;
            float cx = pr.x + 0.5f * pwd, cy = pr.y + 0.5f * pht;
            float4 rg = *(const float4*)(reg + (size_t)row * 4 * NCLS + 4 * p);
            float dx = rg.x / 10.0f, dy = rg.y / 10.0f;
            float dw = fminf(rg.z / 5.0f, XFORM_CLIP);
            float dh = fminf(rg.w / 5.0f, XFORM_CLIP);
            float pcx = dx * pwd + cx, pcy = dy * pht + cy;
            float bw = expf(dw) * pwd, bh = expf(dh) * pht;
            bx.x = fminf(fmaxf(pcx - 0.5f * bw, 0.0f), img_w);
            bx.y = fminf(fmaxf(pcy - 0.5f * bh, 0.0f), img_h);
            bx.z = fminf(fmaxf(pcx + 0.5f * bw, 0.0f), img_w);
            bx.w = fminf(fmaxf(pcy + 0.5f * bh, 0.0f), img_h);
            lab = p;
            lmax = fmaxf(lmax, fmaxf(fmaxf(bx.x, bx.y), fmaxf(bx.z, bx.w)));
        }
        s_box[s] = bx;
        s_score[s] = sc;
        s_label[s] = lab;
    }
    #pragma unroll
    for (int o = 16; o; o >>= 1) lmax = fmaxf(lmax, __shfl_xor_sync(~0u, lmax, o));
    if (lane == 0) sh_red[wid] = lmax;
    __syncthreads();
    if (tid < 32) {
        float v = sh_red[tid];
        #pragma unroll
        for (int o = 16; o; o >>= 1) v = fmaxf(v, __shfl_xor_sync(~0u, v, o));
        if (tid == 0) sh_red[0] = v;
    }
    __syncthreads();
    float mc = sh_red[0];
    for (int s = tid; s < KPRE; s += T) {
        float4 bx = s_box[s];
        float off = (float)s_label[s] * (mc + 1.0f);
        float4 ob = make_float4(bx.x + off, bx.y + off, bx.z + off, bx.w + off);
        s_obox[s] = ob;
        s_area[s] = (ob.z - ob.x) * (ob.w - ob.y);
    }

    // valid bitmask (score > thresh)
    {
        int s0 = wid * 64 + lane;
        u32 v0 = __ballot_sync(~0u, s_score[s0] > SCORE_TH);
        u32 v1 = __ballot_sync(~0u, s_score[s0 + 32] > SCORE_TH);
        if (lane == 0) sh_valid[wid] = ((u64)v1 << 32) | (u64)v0;
    }
    if (tid < 92) sh_ccnt[tid] = 0;
    if (tid == 0) sh_ne = 0;
    __syncthreads();

    // ---- class grouping (only valid candidates) ----
    for (int s = tid; s < KPRE; s += T)
        if (s_score[s] > SCORE_TH) atomicAdd(&sh_ccnt[s_label[s]], 1);
    __syncthreads();
    if (tid == 0) {
        int acc = 0;
        for (int c = 0; c < 92; c++) { sh_cbase[c] = acc; acc += sh_ccnt[c]; }
    }
    __syncthreads();
    if (tid < 92) sh_ccnt[tid] = 0;
    __syncthreads();
    for (int s = tid; s < KPRE; s += T)
        if (s_score[s] > SCORE_TH) {
            int c = s_label[s];
            int pos = atomicAdd(&sh_ccnt[c], 1);
            cls_idx[sh_cbase[c] + pos] = s;
        }
    __syncthreads();

    // ---- suppression-edge generation: only same-class pairs can have IoU>0
    // (class offset makes cross-class boxes exactly disjoint, as in reference)
    for (int c = 1 + wid; c <= NC1; c += 32) {
        int m = sh_ccnt[c];
        int base = sh_cbase[c];
        for (int a = 0; a < m - 1; a++) {
            int u = cls_idx[base + a];
            float4 bu = s_obox[u];
            float au = s_area[u];
            for (int t2 = a + 1 + lane; t2 < m; t2 += 32) {
                int v = cls_idx[base + t2];
                float4 bv = s_obox[v];
                float w = fminf(bu.z, bv.z) - fmaxf(bu.x, bv.x);
                float h = fminf(bu.w, bv.w) - fmaxf(bu.y, bv.y);
                w = fmaxf(w, 0.0f); h = fmaxf(h, 0.0f);
                float inter = w * h;
                if (inter > NMS_TH * (au + s_area[v] - inter)) {
                    int i = u < v ? u : v, j = u < v ? v : u;
                    int e = atomicAdd(&sh_ne, 1);
                    if (e < EDGE_CAP) edges[e] = ((u32)i << 16) | (u32)j;
                }
            }
        }
    }
    __syncthreads();
    int ne = sh_ne; if (ne > EDGE_CAP) ne = EDGE_CAP;

    // ---- edge-list Jacobi fixpoint == sequential greedy (forward edges) ----
    if (tid < 32) sh_kept[tid] = sh_valid[tid];
    __syncthreads();
    for (int it = 0; it < 64; it++) {
        if (tid < 32) sh_sup[tid] = 0ull;
        if (tid == 0) sh_changed = 0;
        __syncthreads();
        for (int e = tid; e < ne; e += T) {
            u32 pk = edges[e];
            int i = pk >> 16, j = pk & 0xFFFF;
            if ((sh_kept[i >> 6] >> (i & 63)) & 1ull)
                atomicOr(&sh_sup[j >> 6], 1ull << (j & 63));
        }
        __syncthreads();
        if (tid < 32) {
            u64 nk = sh_valid[tid] & ~sh_sup[tid];
            if (nk != sh_kept[tid]) { sh_kept[tid] = nk; sh_changed = 1; }
        }
        __syncthreads();
        if (!sh_changed) break;
    }

    // ---- output: defaults then first 100 kept in sorted order ----
    const int soff = B * DETS * 4;
    const int loff = B * DETS * 4 + B * DETS;
    for (int i = tid; i < DETS; i += T) {
        float* bo = out + (size_t)(b * DETS + i) * 4;
        bo[0] = 0.f; bo[1] = 0.f; bo[2] = 0.f; bo[3] = 0.f;
        out[soff + b * DETS + i] = 0.f;
        out[loff + b * DETS + i] = -1.f;
    }
    __syncthreads();

    if (wid == 0) {
        int base = 0;
        for (int w = 0; w < 32 && base < DETS; w++) {
            u64 word = sh_kept[w];
            u32 lo = (u32)word;
            u32 hi = (u32)(word >> 32);
            {
                u32 myb = (lo >> lane) & 1u;
                int pre = __popc(lo & ((1u << lane) - 1u));
                int rank = base + pre;
                if (myb && rank < DETS) {
                    int s = w * 64 + lane;
                    float4 bx = s_box[s];
                    float* bo = out + (size_t)(b * DETS + rank) * 4;
                    bo[0] = bx.x; bo[1] = bx.y; bo[2] = bx.z; bo[3] = bx.w;
                    out[soff + b * DETS + rank] = s_score[s];
                    out[loff + b * DETS + rank] = (float)s_label[s];
                }
                base += __popc(lo);
            }
            {
                u32 myb = (hi >> lane) & 1u;
                int pre = __popc(hi & ((1u << lane) - 1u));
                int rank = base + pre;
                if (myb && rank < DETS) {
                    int s = w * 64 + 32 + lane;
                    float4 bx = s_box[s];
                    float* bo = out + (size_t)(b * DETS + rank) * 4;
                    bo[0] = bx.x; bo[1] = bx.y; bo[2] = bx.z; bo[3] = bx.w;
                    out[soff + b * DETS + rank] = s_score[s];
                    out[loff + b * DETS + rank] = (float)s_label[s];
                }
                base += __popc(hi);
            }
        }
    }
    if (tid == 0) g_cnt[b] = 0;   // reset for next call
}

extern "C" void kernel_launch(void* const* d_in, const int* in_sizes, int n_in,
                              void* d_out, int out_size) {
    const float* logits = (const float*)d_in[0];
    const float* reg = (const float*)d_in[1];
    const float* props = (const float*)d_in[2];
    const void* p_h = d_in[3];
    const void* p_w = d_in[4];
    float* out = (float*)d_out;

    int B = in_sizes[0] / (NPROP * NCLS);
    if (B < 1) B = 1;
    if (B > BMAX) B = BMAX;

    cudaFuncSetAttribute(k_main, cudaFuncAttributeMaxDynamicSharedMemorySize,
                         DYN_BYTES);

    int rows = B * NPROP;
    k_cand<<<(rows + 7) / 8, 256>>>(logits, reg, props, p_h, p_w, B);
    k_main<<<B, 1024, DYN_BYTES>>>(reg, props, p_h, p_w, out, B);
}

// round 9
// speedup vs baseline: 7.4870x; 1.4284x over previous
#include <cuda_runtime.h>
#include <cstdint>

typedef unsigned long long u64;
typedef unsigned int u32;

#define BMAX 8
#define NPROP 4000
#define NCLS 91
#define NC1 90
#define CAP 81920
#define SHCAP 16384
#define KPRE 2048
#define SCORE_TH 0.05f
#define NMS_TH 0.5f
#define XFORM_CLIP 4.135166556742356f
#define DETS 100
#define EDGE_CAP 8192

__device__ int g_cnt[BMAX];   // zero-init at load; reset at end of k_main
__device__ u64 g_keys[BMAX][CAP];

__device__ __forceinline__ float read_dim(const void* p) {
    int v = *(const int*)p;
    if (v > 0 && v < 1000000) return (float)v;
    return *(const float*)p;
}

// FMA-pipe exp (avoids MUFU.EX2 throughput floor). rel err ~2e-6.
__device__ __forceinline__ float fexp(float x) {
    float t = x * 1.4426950408889634f;
    t = fmaxf(t, -126.0f);
    float k = rintf(t);
    float f = t - k;
    float p = 1.3333558146e-3f;
    p = fmaf(p, f, 9.6181291077e-3f);
    p = fmaf(p, f, 5.5504108664e-2f);
    p = fmaf(p, f, 2.4022650695e-1f);
    p = fmaf(p, f, 6.9314718056e-1f);
    p = fmaf(p, f, 1.0f);
    float s = __int_as_float(((int)k + 127) << 23);
    return p * s;
}

// One warp per proposal row; block = 8 rows (never straddles an image since
// 4000 % 8 == 0). Candidates staged in smem; ONE global atomic per block.
__global__ void k_cand(const float* __restrict__ logits,
                       const float* __restrict__ reg,
                       const float* __restrict__ props,
                       const void* __restrict__ p_h,
                       const void* __restrict__ p_w,
                       int B) {
    __shared__ u64 st_keys[768];   // 8 rows x <=90 candidates
    __shared__ int st_cnt, st_base;
    int wid = threadIdx.x >> 5, lane = threadIdx.x & 31;
    int row = blockIdx.x * 8 + wid;
    int b = row / NPROP;
    int n = row - b * NPROP;
    bool live = (row < B * NPROP);

    if (threadIdx.x == 0) st_cnt = 0;
    __syncthreads();

    if (live) {
        const float* lr = logits + (size_t)row * NCLS;
        float l0 = lr[lane];
        float l1 = lr[lane + 32];
        float l2 = (lane < NCLS - 64) ? lr[lane + 64] : -3.0e38f;

        float m = fmaxf(fmaxf(l0, l1), l2);
        #pragma unroll
        for (int o = 16; o; o >>= 1) m = fmaxf(m, __shfl_xor_sync(~0u, m, o));

        float e0 = fexp(l0 - m);
        float e1 = fexp(l1 - m);
        float e2 = (lane < NCLS - 64) ? fexp(l2 - m) : 0.0f;
        float sum = e0 + e1 + e2;
        #pragma unroll
        for (int o = 16; o; o >>= 1) sum += __shfl_xor_sync(~0u, sum, o);
        float inv = 1.0f / sum;

        float img_h = read_dim(p_h);
        float img_w = read_dim(p_w);

        float4 pr = *(const float4*)(props + (size_t)row * 4);
        float pwd = pr.z - pr.x, pht = pr.w - pr.y;
        float cx = pr.x + 0.5f * pwd, cy = pr.y + 0.5f * pht;

        #pragma unroll
        for (int slot = 0; slot < 3; slot++) {
            int p = lane + 32 * slot;
            if (p < 1 || p >= NCLS) continue;
            float e = (slot == 0) ? e0 : (slot == 1 ? e1 : e2);
            float s = e * inv;
            if (s > SCORE_TH) {
                float4 rg = *(const float4*)(reg + (size_t)row * 4 * NCLS + 4 * p);
                float dx = rg.x / 10.0f, dy = rg.y / 10.0f;
                float dw = fminf(rg.z / 5.0f, XFORM_CLIP);
                float dh = fminf(rg.w / 5.0f, XFORM_CLIP);
                float pcx = dx * pwd + cx, pcy = dy * pht + cy;
                float bw = expf(dw) * pwd, bh = expf(dh) * pht;
                float x1 = fminf(fmaxf(pcx - 0.5f * bw, 0.0f), img_w);
                float y1 = fminf(fmaxf(pcy - 0.5f * bh, 0.0f), img_h);
                float x2 = fminf(fmaxf(pcx + 0.5f * bw, 0.0f), img_w);
                float y2 = fminf(fmaxf(pcy + 0.5f * bh, 0.0f), img_h);
                if ((x2 - x1 >= 1.0f) && (y2 - y1 >= 1.0f)) {
                    u32 sb = __float_as_uint(s);
                    u32 mf = (u32)(n * NC1 + (p - 1));
                    u64 key = ((u64)(sb ^ 0xFFFFFFFFu) << 32) | (u64)mf;
                    int idx = atomicAdd(&st_cnt, 1);
                    st_keys[idx] = key;
                }
            }
        }
    }
    __syncthreads();
    int nc = st_cnt;
    if (threadIdx.x == 0 && nc > 0) st_base = atomicAdd(&g_cnt[b], nc);
    __syncthreads();
    if (nc > 0) {
        int base = st_base;
        for (int i = threadIdx.x; i < nc; i += 256)
            if (base + i < CAP) g_keys[b][base + i] = st_keys[i];
    }
}

// dynamic smem: phase 1 = key staging (128KB); phase 2 aliased arrays.
extern __shared__ __align__(16) unsigned char dynbuf[];
#define DYN_BYTES 131072

// One block (1024 thr) per image: 11-bit-window radix-select rank-2048,
// register bitonic sort, fused decode, class-grouped sparse-edge NMS, output.
__global__ void __launch_bounds__(1024, 1)
k_main(const float* __restrict__ reg,
       const float* __restrict__ props,
       const void* __restrict__ p_h,
       const void* __restrict__ p_w,
       float* __restrict__ out, int B) {
    int b = blockIdx.x;
    int tid = threadIdx.x, lane = tid & 31, wid = tid >> 5;
    const int T = 1024;

    __shared__ u64 sh_list[KPRE];          // 16KB (radix bound buffer, then sorted keys)
    __shared__ int h[2048];                // 8KB histogram
    __shared__ int warpsum[32];
    __shared__ u64 sh_prefix;
    __shared__ int sh_rem, sh_nrem, sh_bincnt, sh_binsel;
    __shared__ int sh_curcnt, sh_usebound, sh_done;
    __shared__ int sh_c2, sh_nb;
    __shared__ float sh_red[32];
    __shared__ u64 sh_valid[32], sh_kept[32], sh_sup[32];
    __shared__ int sh_ccnt[92], sh_cbase[92];
    __shared__ int sh_ne, sh_changed;

    u64* keys_sh = (u64*)dynbuf;                      // phase 1 only
    float4* s_obox = (float4*)dynbuf;                 // 32KB
    float4* s_box  = (float4*)(dynbuf + 32768);       // 32KB
    float*  s_area = (float*)(dynbuf + 65536);        // 8KB
    float*  s_score= (float*)(dynbuf + 73728);        // 8KB
    int*    s_label= (int*)(dynbuf + 81920);          // 8KB
    int*    cls_idx= (int*)(dynbuf + 90112);          // 8KB
    u32*    edges  = (u32*)(dynbuf + 98304);          // 32KB -> 8192 edges

    int cnt = g_cnt[b];
    if (cnt > CAP) cnt = CAP;
    bool use_sh = (cnt <= SHCAP);
    const u64* keys = use_sh ? (const u64*)keys_sh : (const u64*)g_keys[b];
    if (use_sh) {
        for (int i = tid; i < cnt; i += T) keys_sh[i] = g_keys[b][i];
    }
    __syncthreads();

    // ---- 11-bit-window radix-select of rank-KPRE key ----
    // windows tile [0,64): shifts 53,42,31,20,9,0 (last window 9 bits).
    u64 thresh = ~0ull;
    if (cnt > KPRE) {
        if (tid == 0) {
            sh_prefix = 0ull; sh_rem = KPRE; sh_curcnt = cnt;
            sh_usebound = 0; sh_done = 0;
        }
        const int shifts[6] = {53, 42, 31, 20, 9, 0};
        for (int p = 0; p < 6; p++) {
            __syncthreads();
            if (sh_done) break;
            int shift = shifts[p];
            u32 bm = (p == 5) ? 0x1FFu : 0x7FFu;
            // zero hist
            h[tid] = 0; h[tid + 1024] = 0;
            __syncthreads();
            u64 prefix = sh_prefix;
            u64 hmask = (p == 0) ? 0ull : (~0ull << shifts[p - 1]);
            int m = sh_curcnt;
            const u64* cur = sh_usebound ? (const u64*)sh_list : keys;
            for (int i = tid; i < m; i += T) {
                u64 k = cur[i];
                if ((k & hmask) == prefix)
                    atomicAdd(&h[(int)((k >> shift) & bm)], 1);
            }
            int rem = sh_rem;   // snapshot BEFORE any thread can update state
            __syncthreads();
            // 2-level scan over 2048 bins (2 bins/thread)
            int a = h[2 * tid], c = h[2 * tid + 1];
            int s = a + c;
            int si = s;
            #pragma unroll
            for (int o = 1; o < 32; o <<= 1) {
                int v = __shfl_up_sync(~0u, si, o);
                if (lane >= o) si += v;
            }
            if (lane == 31) warpsum[wid] = si;
            __syncthreads();
            if (tid < 32) {
                int wv = warpsum[tid];
                #pragma unroll
                for (int o = 1; o < 32; o <<= 1) {
                    int v = __shfl_up_sync(~0u, wv, o);
                    if (tid >= o) wv += v;
                }
                warpsum[tid] = wv;
            }
            __syncthreads();
            int woff = wid ? warpsum[wid - 1] : 0;
            int incl = si + woff;        // inclusive over this thread's pair
            int exclp = incl - s;        // exclusive before bin 2*tid
            if (exclp < rem && rem <= exclp + a) {
                sh_binsel = 2 * tid; sh_bincnt = a; sh_nrem = rem - exclp;
            } else if (exclp + a < rem && rem <= incl) {
                sh_binsel = 2 * tid + 1; sh_bincnt = c; sh_nrem = rem - exclp - a;
            }
            __syncthreads();
            int bin = sh_binsel, bc = sh_bincnt, nrem = sh_nrem;
            u64 pfull = prefix | ((u64)bin << shift);
            if (tid == 0) { sh_prefix = pfull; sh_rem = nrem; }
            if (bc == nrem) {
                // whole bin included: threshold = pfull with low bits all 1
                if (tid == 0) {
                    sh_prefix = pfull | ((shift == 0) ? 0ull : ((1ull << shift) - 1ull));
                    sh_done = 1;
                }
            } else if (!sh_usebound && bc <= KPRE && p < 5) {
                // compact boundary set into sh_list (once)
                if (tid == 0) sh_nb = 0;
                __syncthreads();
                u64 fmask = ~((1ull << shift) - 1ull);
                for (int i = tid; i < m; i += T) {
                    u64 k = cur[i];
                    if ((k & fmask) == pfull) {
                        int pos = atomicAdd(&sh_nb, 1);
                        sh_list[pos] = k;
                    }
                }
                __syncthreads();
                if (tid == 0) { sh_curcnt = bc; sh_usebound = 1; }
            }
        }
        __syncthreads();
        thresh = sh_prefix;
    }

    // ---- collect exactly KPRE keys <= thresh ----
    if (tid == 0) sh_c2 = 0;
    __syncthreads();
    for (int i = tid; i < cnt; i += T) {
        u64 k = keys[i];
        if (k <= thresh) {
            int pos = atomicAdd(&sh_c2, 1);
            if (pos < KPRE) sh_list[pos] = k;
        }
    }
    __syncthreads();
    int got = sh_c2; if (got > KPRE) got = KPRE;
    for (int t = got + tid; t < KPRE; t += T) sh_list[t] = ~0ull;
    __syncthreads();

    // ---- register bitonic sort: 2 elems/thread ----
    {
        u64 v0 = sh_list[tid], v1 = sh_list[tid + 1024];
        const int i0 = tid, i1 = tid + 1024;
        for (int size = 2; size <= KPRE; size <<= 1) {
            for (int stride = size >> 1; stride > 0; stride >>= 1) {
                if (stride == 1024) {
                    u64 a = v0 < v1 ? v0 : v1;
                    u64 c = v0 < v1 ? v1 : v0;
                    v0 = a; v1 = c;
                } else if (stride >= 32) {
                    sh_list[i0] = v0; sh_list[i1] = v1;
                    __syncthreads();
                    u64 p0 = sh_list[i0 ^ stride];
                    u64 p1 = sh_list[i1 ^ stride];
                    bool tm0 = ((i0 & size) == 0) ^ ((i0 & stride) != 0);
                    bool tm1 = ((i1 & size) == 0) ^ ((i1 & stride) != 0);
                    v0 = tm0 ? (v0 < p0 ? v0 : p0) : (v0 < p0 ? p0 : v0);
                    v1 = tm1 ? (v1 < p1 ? v1 : p1) : (v1 < p1 ? p1 : v1);
                    __syncthreads();
                } else {
                    u64 p0 = __shfl_xor_sync(~0u, v0, stride);
                    u64 p1 = __shfl_xor_sync(~0u, v1, stride);
                    bool tm0 = ((i0 & size) == 0) ^ ((i0 & stride) != 0);
                    bool tm1 = ((i1 & size) == 0) ^ ((i1 & stride) != 0);
                    v0 = tm0 ? (v0 < p0 ? v0 : p0) : (v0 < p0 ? p0 : v0);
                    v1 = tm1 ? (v1 < p1 ? v1 : p1) : (v1 < p1 ? p1 : v1);
                }
            }
        }
        sh_list[i0] = v0; sh_list[i1] = v1;
        __syncthreads();
    }

    // ---- fused decode into smem (aliases key staging; keys consumed) ----
    float img_h = read_dim(p_h);
    float img_w = read_dim(p_w);
    float lmax = 0.0f;
    for (int s = tid; s < KPRE; s += T) {
        u64 k = sh_list[s];
        float4 bx = make_float4(0.f, 0.f, 0.f, 0.f);
        float sc = -1.0f;
        int lab = 0;
        if (k != ~0ull) {
            u32 mf = (u32)(k & 0xFFFFFFFFu);
            sc = __uint_as_float(~((u32)(k >> 32)));
            int n = (int)(mf / NC1);
            int p = (int)(mf - (u32)n * NC1) + 1;
            int row = b * NPROP + n;
            float4 pr = *(const float4*)(props + (size_t)row * 4);
            float pwd = pr.z - pr.x, pht = pr.w - pr.y;
            float cx = pr.x + 0.5f * pwd, cy = pr.y + 0.5f * pht;
            float4 rg = *(const float4*)(reg + (size_t)row * 4 * NCLS + 4 * p);
            float dx = rg.x / 10.0f, dy = rg.y / 10.0f;
            float dw = fminf(rg.z / 5.0f, XFORM_CLIP);
            float dh = fminf(rg.w / 5.0f, XFORM_CLIP);
            float pcx = dx * pwd + cx, pcy = dy * pht + cy;
            float bw = expf(dw) * pwd, bh = expf(dh) * pht;
            bx.x = fminf(fmaxf(pcx - 0.5f * bw, 0.0f), img_w);
            bx.y = fminf(fmaxf(pcy - 0.5f * bh, 0.0f), img_h);
            bx.z = fminf(fmaxf(pcx + 0.5f * bw, 0.0f), img_w);
            bx.w = fminf(fmaxf(pcy + 0.5f * bh, 0.0f), img_h);
            lab = p;
            lmax = fmaxf(lmax, fmaxf(fmaxf(bx.x, bx.y), fmaxf(bx.z, bx.w)));
        }
        s_box[s] = bx;
        s_score[s] = sc;
        s_label[s] = lab;
    }
    #pragma unroll
    for (int o = 16; o; o >>= 1) lmax = fmaxf(lmax, __shfl_xor_sync(~0u, lmax, o));
    if (lane == 0) sh_red[wid] = lmax;
    __syncthreads();
    if (tid < 32) {
        float v = sh_red[tid];
        #pragma unroll
        for (int o = 16; o; o >>= 1) v = fmaxf(v, __shfl_xor_sync(~0u, v, o));
        if (tid == 0) sh_red[0] = v;
    }
    __syncthreads();
    float mc = sh_red[0];
    for (int s = tid; s < KPRE; s += T) {
        float4 bx = s_box[s];
        float off = (float)s_label[s] * (mc + 1.0f);
        float4 ob = make_float4(bx.x + off, bx.y + off, bx.z + off, bx.w + off);
        s_obox[s] = ob;
        s_area[s] = (ob.z - ob.x) * (ob.w - ob.y);
    }

    // valid bitmask (score > thresh)
    {
        int s0 = wid * 64 + lane;
        u32 v0 = __ballot_sync(~0u, s_score[s0] > SCORE_TH);
        u32 v1 = __ballot_sync(~0u, s_score[s0 + 32] > SCORE_TH);
        if (lane == 0) sh_valid[wid] = ((u64)v1 << 32) | (u64)v0;
    }
    if (tid < 92) sh_ccnt[tid] = 0;
    if (tid == 0) sh_ne = 0;
    __syncthreads();

    // ---- class grouping (only valid candidates) ----
    for (int s = tid; s < KPRE; s += T)
        if (s_score[s] > SCORE_TH) atomicAdd(&sh_ccnt[s_label[s]], 1);
    __syncthreads();
    if (tid == 0) {
        int acc = 0;
        for (int c = 0; c < 92; c++) { sh_cbase[c] = acc; acc += sh_ccnt[c]; }
    }
    __syncthreads();
    if (tid < 92) sh_ccnt[tid] = 0;
    __syncthreads();
    for (int s = tid; s < KPRE; s += T)
        if (s_score[s] > SCORE_TH) {
            int c = s_label[s];
            int pos = atomicAdd(&sh_ccnt[c], 1);
            cls_idx[sh_cbase[c] + pos] = s;
        }
    __syncthreads();

    // ---- suppression-edge generation: only same-class pairs can have IoU>0
    for (int c = 1 + wid; c <= NC1; c += 32) {
        int m = sh_ccnt[c];
        int base = sh_cbase[c];
        for (int a = 0; a < m - 1; a++) {
            int u = cls_idx[base + a];
            float4 bu = s_obox[u];
            float au = s_area[u];
            for (int t2 = a + 1 + lane; t2 < m; t2 += 32) {
                int v = cls_idx[base + t2];
                float4 bv = s_obox[v];
                float w = fminf(bu.z, bv.z) - fmaxf(bu.x, bv.x);
                float h2 = fminf(bu.w, bv.w) - fmaxf(bu.y, bv.y);
                w = fmaxf(w, 0.0f); h2 = fmaxf(h2, 0.0f);
                float inter = w * h2;
                if (inter > NMS_TH * (au + s_area[v] - inter)) {
                    int i = u < v ? u : v, j = u < v ? v : u;
                    int e = atomicAdd(&sh_ne, 1);
                    if (e < EDGE_CAP) edges[e] = ((u32)i << 16) | (u32)j;
                }
            }
        }
    }
    __syncthreads();
    int ne = sh_ne; if (ne > EDGE_CAP) ne = EDGE_CAP;

    // ---- edge-list Jacobi fixpoint == sequential greedy (forward edges) ----
    if (tid < 32) sh_kept[tid] = sh_valid[tid];
    __syncthreads();
    for (int it = 0; it < 64; it++) {
        if (tid < 32) sh_sup[tid] = 0ull;
        if (tid == 0) sh_changed = 0;
        __syncthreads();
        for (int e = tid; e < ne; e += T) {
            u32 pk = edges[e];
            int i = pk >> 16, j = pk & 0xFFFF;
            if ((sh_kept[i >> 6] >> (i & 63)) & 1ull)
                atomicOr(&sh_sup[j >> 6], 1ull << (j & 63));
        }
        __syncthreads();
        if (tid < 32) {
            u64 nk = sh_valid[tid] & ~sh_sup[tid];
            if (nk != sh_kept[tid]) { sh_kept[tid] = nk; sh_changed = 1; }
        }
        __syncthreads();
        if (!sh_changed) break;
    }

    // ---- output: defaults then first 100 kept in sorted order ----
    const int soff = B * DETS * 4;
    const int loff = B * DETS * 4 + B * DETS;
    for (int i = tid; i < DETS; i += T) {
        float* bo = out + (size_t)(b * DETS + i) * 4;
        bo[0] = 0.f; bo[1] = 0.f; bo[2] = 0.f; bo[3] = 0.f;
        out[soff + b * DETS + i] = 0.f;
        out[loff + b * DETS + i] = -1.f;
    }
    __syncthreads();

    if (wid == 0) {
        int base = 0;
        for (int w = 0; w < 32 && base < DETS; w++) {
            u64 word = sh_kept[w];
            u32 lo = (u32)word;
            u32 hi = (u32)(word >> 32);
            {
                u32 myb = (lo >> lane) & 1u;
                int pre = __popc(lo & ((1u << lane) - 1u));
                int rank = base + pre;
                if (myb && rank < DETS) {
                    int s = w * 64 + lane;
                    float4 bx = s_box[s];
                    float* bo = out + (size_t)(b * DETS + rank) * 4;
                    bo[0] = bx.x; bo[1] = bx.y; bo[2] = bx.z; bo[3] = bx.w;
                    out[soff + b * DETS + rank] = s_score[s];
                    out[loff + b * DETS + rank] = (float)s_label[s];
                }
                base += __popc(lo);
            }
            {
                u32 myb = (hi >> lane) & 1u;
                int pre = __popc(hi & ((1u << lane) - 1u));
                int rank = base + pre;
                if (myb && rank < DETS) {
                    int s = w * 64 + 32 + lane;
                    float4 bx = s_box[s];
                    float* bo = out + (size_t)(b * DETS + rank) * 4;
                    bo[0] = bx.x; bo[1] = bx.y; bo[2] = bx.z; bo[3] = bx.w;
                    out[soff + b * DETS + rank] = s_score[s];
                    out[loff + b * DETS + rank] = (float)s_label[s];
                }
                base += __popc(hi);
            }
        }
    }
    if (tid == 0) g_cnt[b] = 0;   // reset for next call
}

extern "C" void kernel_launch(void* const* d_in, const int* in_sizes, int n_in,
                              void* d_out, int out_size) {
    const float* logits = (const float*)d_in[0];
    const float* reg = (const float*)d_in[1];
    const float* props = (const float*)d_in[2];
    const void* p_h = d_in[3];
    const void* p_w = d_in[4];
    float* out = (float*)d_out;

    int B = in_sizes[0] / (NPROP * NCLS);
    if (B < 1) B = 1;
    if (B > BMAX) B = BMAX;

    cudaFuncSetAttribute(k_main, cudaFuncAttributeMaxDynamicSharedMemorySize,
                         DYN_BYTES);

    int rows = B * NPROP;
    k_cand<<<(rows + 7) / 8, 256>>>(logits, reg, props, p_h, p_w, B);
    k_main<<<B, 1024, DYN_BYTES>>>(reg, props, p_h, p_w, out, B);
}

// round 10
// speedup vs baseline: 8.7328x; 1.1664x over previous
#include <cuda_runtime.h>
#include <cstdint>

typedef unsigned long long u64;
typedef unsigned int u32;

#define BMAX 8
#define NPROP 4000
#define NCLS 91
#define NC1 90
#define CAP 81920
#define SHCAP 16384
#define KPRE 2048
#define SCORE_TH 0.05f
#define NMS_TH 0.5f
#define XFORM_CLIP 4.135166556742356f
#define DETS 100
#define EDGE_CAP 8192

__device__ int g_cnt[BMAX];
__device__ u64 g_keys[BMAX][CAP];
__device__ float4 g_box[BMAX][KPRE];
__device__ float4 g_obox[BMAX][KPRE];
__device__ float g_score[BMAX][KPRE];
__device__ int g_label[BMAX][KPRE];
__device__ u64 g_skey[BMAX][KPRE];
__device__ int g_ccnt[BMAX][NCLS + 1];
__device__ int g_cbase[BMAX][NCLS + 1];
__device__ int g_clsidx[BMAX][KPRE];
__device__ int g_ne[BMAX];
__device__ u32 g_edges[BMAX][EDGE_CAP];

__device__ __forceinline__ float read_dim(const void* p) {
    int v = *(const int*)p;
    if (v > 0 && v < 1000000) return (float)v;
    return *(const float*)p;
}

// FMA-pipe exp (avoids MUFU.EX2 throughput floor). rel err ~2e-6.
__device__ __forceinline__ float fexp(float x) {
    float t = x * 1.4426950408889634f;
    t = fmaxf(t, -126.0f);
    float k = rintf(t);
    float f = t - k;
    float p = 1.3333558146e-3f;
    p = fmaf(p, f, 9.6181291077e-3f);
    p = fmaf(p, f, 5.5504108664e-2f);
    p = fmaf(p, f, 2.4022650695e-1f);
    p = fmaf(p, f, 6.9314718056e-1f);
    p = fmaf(p, f, 1.0f);
    float s = __int_as_float(((int)k + 127) << 23);
    return p * s;
}

// ---------------- k_cand: unchanged (proven win) ----------------
__global__ void k_cand(const float* __restrict__ logits,
                       const float* __restrict__ reg,
                       const float* __restrict__ props,
                       const void* __restrict__ p_h,
                       const void* __restrict__ p_w,
                       int B) {
    __shared__ u64 st_keys[768];
    __shared__ int st_cnt, st_base;
    int wid = threadIdx.x >> 5, lane = threadIdx.x & 31;
    int row = blockIdx.x * 8 + wid;
    int b = row / NPROP;
    int n = row - b * NPROP;
    bool live = (row < B * NPROP);

    if (threadIdx.x == 0) st_cnt = 0;
    __syncthreads();

    if (live) {
        const float* lr = logits + (size_t)row * NCLS;
        float l0 = lr[lane];
        float l1 = lr[lane + 32];
        float l2 = (lane < NCLS - 64) ? lr[lane + 64] : -3.0e38f;

        float m = fmaxf(fmaxf(l0, l1), l2);
        #pragma unroll
        for (int o = 16; o; o >>= 1) m = fmaxf(m, __shfl_xor_sync(~0u, m, o));

        float e0 = fexp(l0 - m);
        float e1 = fexp(l1 - m);
        float e2 = (lane < NCLS - 64) ? fexp(l2 - m) : 0.0f;
        float sum = e0 + e1 + e2;
        #pragma unroll
        for (int o = 16; o; o >>= 1) sum += __shfl_xor_sync(~0u, sum, o);
        float inv = 1.0f / sum;

        float img_h = read_dim(p_h);
        float img_w = read_dim(p_w);

        float4 pr = *(const float4*)(props + (size_t)row * 4);
        float pwd = pr.z - pr.x, pht = pr.w - pr.y;
        float cx = pr.x + 0.5f * pwd, cy = pr.y + 0.5f * pht;

        #pragma unroll
        for (int slot = 0; slot < 3; slot++) {
            int p = lane + 32 * slot;
            if (p < 1 || p >= NCLS) continue;
            float e = (slot == 0) ? e0 : (slot == 1 ? e1 : e2);
            float s = e * inv;
            if (s > SCORE_TH) {
                float4 rg = *(const float4*)(reg + (size_t)row * 4 * NCLS + 4 * p);
                float dx = rg.x / 10.0f, dy = rg.y / 10.0f;
                float dw = fminf(rg.z / 5.0f, XFORM_CLIP);
                float dh = fminf(rg.w / 5.0f, XFORM_CLIP);
                float pcx = dx * pwd + cx, pcy = dy * pht + cy;
                float bw = expf(dw) * pwd, bh = expf(dh) * pht;
                float x1 = fminf(fmaxf(pcx - 0.5f * bw, 0.0f), img_w);
                float y1 = fminf(fmaxf(pcy - 0.5f * bh, 0.0f), img_h);
                float x2 = fminf(fmaxf(pcx + 0.5f * bw, 0.0f), img_w);
                float y2 = fminf(fmaxf(pcy + 0.5f * bh, 0.0f), img_h);
                if ((x2 - x1 >= 1.0f) && (y2 - y1 >= 1.0f)) {
                    u32 sb = __float_as_uint(s);
                    u32 mf = (u32)(n * NC1 + (p - 1));
                    u64 key = ((u64)(sb ^ 0xFFFFFFFFu) << 32) | (u64)mf;
                    int idx = atomicAdd(&st_cnt, 1);
                    st_keys[idx] = key;
                }
            }
        }
    }
    __syncthreads();
    int nc = st_cnt;
    if (threadIdx.x == 0 && nc > 0) st_base = atomicAdd(&g_cnt[b], nc);
    __syncthreads();
    if (nc > 0) {
        int base = st_base;
        for (int i = threadIdx.x; i < nc; i += 256)
            if (base + i < CAP) g_keys[b][base + i] = st_keys[i];
    }
}

extern __shared__ __align__(16) unsigned char dynbuf[];
#define DYN_A 131072
#define DYN_C 49152

// ---------------- Kernel A: select top-2048 (UNSORTED) + decode + class group
__global__ void __launch_bounds__(1024, 1)
k_select(const float* __restrict__ reg,
         const float* __restrict__ props,
         const void* __restrict__ p_h,
         const void* __restrict__ p_w,
         int B) {
    int b = blockIdx.x;
    int tid = threadIdx.x, lane = tid & 31, wid = tid >> 5;
    const int T = 1024;

    __shared__ u64 sh_list[KPRE];
    __shared__ int h[2048];
    __shared__ int warpsum[32];
    __shared__ u64 sh_prefix;
    __shared__ int sh_rem, sh_nrem, sh_bincnt, sh_binsel;
    __shared__ int sh_curcnt, sh_usebound, sh_done;
    __shared__ int sh_c2, sh_nb;
    __shared__ float sh_red[32];
    __shared__ int sh_ccnt[NCLS + 1], sh_cbase[NCLS + 1];

    u64* keys_sh = (u64*)dynbuf;

    if (tid == 0) g_ne[b] = 0;

    int cnt = g_cnt[b];
    if (cnt > CAP) cnt = CAP;
    bool use_sh = (cnt <= SHCAP);
    const u64* keys = use_sh ? (const u64*)keys_sh : (const u64*)g_keys[b];
    if (use_sh) {
        for (int i = tid; i < cnt; i += T) keys_sh[i] = g_keys[b][i];
    }
    __syncthreads();

    // ---- 11-bit-window radix select rank-KPRE (windows 53,42,31,20,9,0) ----
    u64 thresh = ~0ull;
    if (cnt > KPRE) {
        if (tid == 0) {
            sh_prefix = 0ull; sh_rem = KPRE; sh_curcnt = cnt;
            sh_usebound = 0; sh_done = 0;
        }
        const int shifts[6] = {53, 42, 31, 20, 9, 0};
        for (int p = 0; p < 6; p++) {
            __syncthreads();
            if (sh_done) break;
            int shift = shifts[p];
            u32 bm = (p == 5) ? 0x1FFu : 0x7FFu;
            h[tid] = 0; h[tid + 1024] = 0;
            __syncthreads();
            u64 prefix = sh_prefix;
            u64 hmask = (p == 0) ? 0ull : (~0ull << shifts[p - 1]);
            int m = sh_curcnt;
            const u64* cur = sh_usebound ? (const u64*)sh_list : keys;
            for (int i = tid; i < m; i += T) {
                u64 k = cur[i];
                if ((k & hmask) == prefix)
                    atomicAdd(&h[(int)((k >> shift) & bm)], 1);
            }
            int rem = sh_rem;
            __syncthreads();
            int a = h[2 * tid], c = h[2 * tid + 1];
            int s = a + c;
            int si = s;
            #pragma unroll
            for (int o = 1; o < 32; o <<= 1) {
                int v = __shfl_up_sync(~0u, si, o);
                if (lane >= o) si += v;
            }
            if (lane == 31) warpsum[wid] = si;
            __syncthreads();
            if (tid < 32) {
                int wv = warpsum[tid];
                #pragma unroll
                for (int o = 1; o < 32; o <<= 1) {
                    int v = __shfl_up_sync(~0u, wv, o);
                    if (tid >= o) wv += v;
                }
                warpsum[tid] = wv;
            }
            __syncthreads();
            int woff = wid ? warpsum[wid - 1] : 0;
            int incl = si + woff;
            int exclp = incl - s;
            if (exclp < rem && rem <= exclp + a) {
                sh_binsel = 2 * tid; sh_bincnt = a; sh_nrem = rem - exclp;
            } else if (exclp + a < rem && rem <= incl) {
                sh_binsel = 2 * tid + 1; sh_bincnt = c; sh_nrem = rem - exclp - a;
            }
            __syncthreads();
            int bin = sh_binsel, bc = sh_bincnt, nrem = sh_nrem;
            u64 pfull = prefix | ((u64)bin << shift);
            if (tid == 0) { sh_prefix = pfull; sh_rem = nrem; }
            if (bc == nrem) {
                if (tid == 0) {
                    sh_prefix = pfull | ((shift == 0) ? 0ull : ((1ull << shift) - 1ull));
                    sh_done = 1;
                }
            } else if (!sh_usebound && bc <= KPRE && p < 5) {
                if (tid == 0) sh_nb = 0;
                __syncthreads();
                u64 fmask = ~((1ull << shift) - 1ull);
                for (int i = tid; i < m; i += T) {
                    u64 k = cur[i];
                    if ((k & fmask) == pfull) {
                        int pos = atomicAdd(&sh_nb, 1);
                        sh_list[pos] = k;
                    }
                }
                __syncthreads();
                if (tid == 0) { sh_curcnt = bc; sh_usebound = 1; }
            }
        }
        __syncthreads();
        thresh = sh_prefix;
    }

    // ---- collect (UNSORTED), warp-aggregated atomics, padded loop ----
    if (tid == 0) sh_c2 = 0;
    __syncthreads();
    for (int i0 = 0; i0 < cnt; i0 += T) {
        int i = i0 + tid;
        bool in = (i < cnt);
        u64 k = in ? keys[i] : ~0ull;
        bool hit = in && (k <= thresh);
        u32 bal = __ballot_sync(~0u, hit);
        int base = 0;
        if (lane == 0 && bal) base = atomicAdd(&sh_c2, __popc(bal));
        base = __shfl_sync(~0u, base, 0);
        if (hit) {
            int pos = base + __popc(bal & ((1u << lane) - 1u));
            if (pos < KPRE) sh_list[pos] = k;
        }
    }
    __syncthreads();
    int ncol = sh_c2; if (ncol > KPRE) ncol = KPRE;

    // ---- decode (2 slots/thread, boxes kept in registers across mc pass) ----
    float img_h = read_dim(p_h);
    float img_w = read_dim(p_w);
    float lmax = 0.0f;
    float4 rbx[2];
    int rlab[2];
    #pragma unroll
    for (int q = 0; q < 2; q++) {
        int s = tid + q * 1024;
        float4 bx = make_float4(0.f, 0.f, 0.f, 0.f);
        float sc = -1.0f;
        int lab = 0;
        u64 k = ~0ull;
        if (s < ncol) {
            k = sh_list[s];
            u32 mf = (u32)(k & 0xFFFFFFFFu);
            sc = __uint_as_float(~((u32)(k >> 32)));
            int n = (int)(mf / NC1);
            int p = (int)(mf - (u32)n * NC1) + 1;
            int row = b * NPROP + n;
            float4 pr = *(const float4*)(props + (size_t)row * 4);
            float pwd = pr.z - pr.x, pht = pr.w - pr.y;
            float cx = pr.x + 0.5f * pwd, cy = pr.y + 0.5f * pht;
            float4 rg = *(const float4*)(reg + (size_t)row * 4 * NCLS + 4 * p);
            float dx = rg.x / 10.0f, dy = rg.y / 10.0f;
            float dw = fminf(rg.z / 5.0f, XFORM_CLIP);
            float dh = fminf(rg.w / 5.0f, XFORM_CLIP);
            float pcx = dx * pwd + cx, pcy = dy * pht + cy;
            float bw = expf(dw) * pwd, bh = expf(dh) * pht;
            bx.x = fminf(fmaxf(pcx - 0.5f * bw, 0.0f), img_w);
            bx.y = fminf(fmaxf(pcy - 0.5f * bh, 0.0f), img_h);
            bx.z = fminf(fmaxf(pcx + 0.5f * bw, 0.0f), img_w);
            bx.w = fminf(fmaxf(pcy + 0.5f * bh, 0.0f), img_h);
            lab = p;
            lmax = fmaxf(lmax, fmaxf(fmaxf(bx.x, bx.y), fmaxf(bx.z, bx.w)));
        }
        rbx[q] = bx; rlab[q] = lab;
        g_box[b][s] = bx;
        g_score[b][s] = sc;
        g_label[b][s] = lab;
        g_skey[b][s] = k;
    }
    #pragma unroll
    for (int o = 16; o; o >>= 1) lmax = fmaxf(lmax, __shfl_xor_sync(~0u, lmax, o));
    if (lane == 0) sh_red[wid] = lmax;
    __syncthreads();
    if (tid < 32) {
        float v = sh_red[tid];
        #pragma unroll
        for (int o = 16; o; o >>= 1) v = fmaxf(v, __shfl_xor_sync(~0u, v, o));
        if (tid == 0) sh_red[0] = v;
    }
    __syncthreads();
    float mc = sh_red[0];
    #pragma unroll
    for (int q = 0; q < 2; q++) {
        int s = tid + q * 1024;
        float off = (float)rlab[q] * (mc + 1.0f);
        float4 bx = rbx[q];
        g_obox[b][s] = make_float4(bx.x + off, bx.y + off, bx.z + off, bx.w + off);
    }

    // ---- class grouping ----
    if (tid <= NCLS) sh_ccnt[tid] = 0;
    __syncthreads();
    #pragma unroll
    for (int q = 0; q < 2; q++) {
        int s = tid + q * 1024;
        if (s < ncol) atomicAdd(&sh_ccnt[rlab[q]], 1);
    }
    __syncthreads();
    if (tid == 0) {
        int acc = 0;
        for (int c = 0; c <= NCLS; c++) { sh_cbase[c] = acc; acc += sh_ccnt[c]; }
    }
    __syncthreads();
    if (tid <= NCLS) {
        g_ccnt[b][tid] = sh_ccnt[tid];
        g_cbase[b][tid] = sh_cbase[tid];
        sh_ccnt[tid] = 0;
    }
    __syncthreads();
    #pragma unroll
    for (int q = 0; q < 2; q++) {
        int s = tid + q * 1024;
        if (s < ncol) {
            int c = rlab[q];
            int pos = atomicAdd(&sh_ccnt[c], 1);
            g_clsidx[b][sh_cbase[c] + pos] = s;
        }
    }
}

// ---------------- Kernel B: per-(class,image) suppression edges ----------------
__global__ void k_edges(int B) {
    int c = blockIdx.x + 1;
    int b = blockIdx.y;
    int t = threadIdx.x;  // 32
    int m = g_ccnt[b][c];
    if (m < 2) return;
    int base = g_cbase[b][c];
    for (int a = 0; a < m - 1; a++) {
        int u = g_clsidx[b][base + a];
        float4 bu = g_obox[b][u];
        float au = (bu.z - bu.x) * (bu.w - bu.y);
        u64 ku = g_skey[b][u];
        for (int t2 = a + 1 + t; t2 < m; t2 += 32) {
            int v = g_clsidx[b][base + t2];
            float4 bv = g_obox[b][v];
            float w = fminf(bu.z, bv.z) - fmaxf(bu.x, bv.x);
            float h2 = fminf(bu.w, bv.w) - fmaxf(bu.y, bv.y);
            w = fmaxf(w, 0.0f); h2 = fmaxf(h2, 0.0f);
            float inter = w * h2;
            float av = (bv.z - bv.x) * (bv.w - bv.y);
            if (inter > NMS_TH * (au + av - inter)) {
                u64 kv = g_skey[b][v];
                int i = (ku < kv) ? u : v;
                int j = (ku < kv) ? v : u;
                int e = atomicAdd(&g_ne[b], 1);
                if (e < EDGE_CAP) g_edges[b][e] = ((u32)i << 16) | (u32)j;
            }
        }
    }
}

// ---------------- Kernel C: Jacobi NMS + rank-100 + output ----------------
__global__ void __launch_bounds__(1024, 1)
k_nms(float* __restrict__ out, int B) {
    int b = blockIdx.x;
    int tid = threadIdx.x, lane = tid & 31, wid = tid >> 5;
    const int T = 1024;

    __shared__ int h[2048];
    __shared__ int warpsum[32];
    __shared__ u64 sh_prefix;
    __shared__ int sh_rem, sh_nrem, sh_bincnt, sh_binsel, sh_done;
    __shared__ u64 sh_valid[32], sh_kept[32], sh_sup[32];
    __shared__ int sh_changed, sh_nkept, sh_nsel;
    __shared__ int sel[128];

    u64* skeys = (u64*)dynbuf;                 // 16KB
    u32* edges = (u32*)(dynbuf + 16384);       // 32KB

    // load keys + edges to smem
    #pragma unroll
    for (int q = 0; q < 2; q++) {
        int s = tid + q * 1024;
        skeys[s] = g_skey[b][s];
    }
    int ne = g_ne[b]; if (ne > EDGE_CAP) ne = EDGE_CAP;
    for (int e = tid; e < ne; e += T) edges[e] = g_edges[b][e];
    __syncthreads();

    // valid = real slot (pads have key ~0)
    {
        int s0 = wid * 64 + lane;
        u32 v0 = __ballot_sync(~0u, skeys[s0] != ~0ull);
        u32 v1 = __ballot_sync(~0u, skeys[s0 + 32] != ~0ull);
        if (lane == 0) {
            u64 v = ((u64)v1 << 32) | (u64)v0;
            sh_valid[wid] = v;
            sh_kept[wid] = v;
        }
    }
    __syncthreads();

    // Jacobi fixpoint == greedy (edges form a DAG by key order)
    for (int it = 0; it < 64; it++) {
        if (tid < 32) sh_sup[tid] = 0ull;
        if (tid == 0) sh_changed = 0;
        __syncthreads();
        for (int e = tid; e < ne; e += T) {
            u32 pk = edges[e];
            int i = pk >> 16, j = pk & 0xFFFF;
            if ((sh_kept[i >> 6] >> (i & 63)) & 1ull)
                atomicOr(&sh_sup[j >> 6], 1ull << (j & 63));
        }
        __syncthreads();
        if (tid < 32) {
            u64 nk = sh_valid[tid] & ~sh_sup[tid];
            if (nk != sh_kept[tid]) { sh_kept[tid] = nk; sh_changed = 1; }
        }
        __syncthreads();
        if (!sh_changed) break;
    }

    // count kept
    if (tid < 32) {
        int c = __popcll(sh_kept[tid]);
        #pragma unroll
        for (int o = 16; o; o >>= 1) c += __shfl_xor_sync(~0u, c, o);
        if (tid == 0) sh_nkept = c;
    }
    __syncthreads();
    int nkept = sh_nkept;
    int want = nkept < DETS ? nkept : DETS;

    // defaults
    const int soff = B * DETS * 4;
    const int loff = B * DETS * 4 + B * DETS;
    for (int i = tid; i < DETS; i += T) {
        float* bo = out + (size_t)(b * DETS + i) * 4;
        bo[0] = 0.f; bo[1] = 0.f; bo[2] = 0.f; bo[3] = 0.f;
        out[soff + b * DETS + i] = 0.f;
        out[loff + b * DETS + i] = -1.f;
    }

    if (want > 0) {
        // radix-select rank-want key among KEPT keys
        u64 thresh = ~0ull;
        if (nkept > want) {
            if (tid == 0) { sh_prefix = 0ull; sh_rem = want; sh_done = 0; }
            const int shifts[6] = {53, 42, 31, 20, 9, 0};
            for (int p = 0; p < 6; p++) {
                __syncthreads();
                if (sh_done) break;
                int shift = shifts[p];
                u32 bm = (p == 5) ? 0x1FFu : 0x7FFu;
                h[tid] = 0; h[tid + 1024] = 0;
                __syncthreads();
                u64 prefix = sh_prefix;
                u64 hmask = (p == 0) ? 0ull : (~0ull << shifts[p - 1]);
                #pragma unroll
                for (int q = 0; q < 2; q++) {
                    int s = tid + q * 1024;
                    if ((sh_kept[s >> 6] >> (s & 63)) & 1ull) {
                        u64 k = skeys[s];
                        if ((k & hmask) == prefix)
                            atomicAdd(&h[(int)((k >> shift) & bm)], 1);
                    }
                }
                int rem = sh_rem;
                __syncthreads();
                int a = h[2 * tid], c = h[2 * tid + 1];
                int s2 = a + c;
                int si = s2;
                #pragma unroll
                for (int o = 1; o < 32; o <<= 1) {
                    int v = __shfl_up_sync(~0u, si, o);
                    if (lane >= o) si += v;
                }
                if (lane == 31) warpsum[wid] = si;
                __syncthreads();
                if (tid < 32) {
                    int wv = warpsum[tid];
                    #pragma unroll
                    for (int o = 1; o < 32; o <<= 1) {
                        int v = __shfl_up_sync(~0u, wv, o);
                        if (tid >= o) wv += v;
                    }
                    warpsum[tid] = wv;
                }
                __syncthreads();
                int woff = wid ? warpsum[wid - 1] : 0;
                int incl = si + woff;
                int exclp = incl - s2;
                if (exclp < rem && rem <= exclp + a) {
                    sh_binsel = 2 * tid; sh_bincnt = a; sh_nrem = rem - exclp;
                } else if (exclp + a < rem && rem <= incl) {
                    sh_binsel = 2 * tid + 1; sh_bincnt = c; sh_nrem = rem - exclp - a;
                }
                __syncthreads();
                int bin = sh_binsel, bc = sh_bincnt, nrem = sh_nrem;
                u64 pfull = prefix | ((u64)bin << shift);
                if (tid == 0) { sh_prefix = pfull; sh_rem = nrem; }
                if (bc == nrem) {
                    if (tid == 0) {
                        sh_prefix = pfull | ((shift == 0) ? 0ull : ((1ull << shift) - 1ull));
                        sh_done = 1;
                    }
                }
            }
            __syncthreads();
            thresh = sh_prefix;
        }

        // collect kept keys <= thresh (exactly `want`, keys unique)
        if (tid == 0) sh_nsel = 0;
        __syncthreads();
        #pragma unroll
        for (int q = 0; q < 2; q++) {
            int s = tid + q * 1024;
            bool hit = ((sh_kept[s >> 6] >> (s & 63)) & 1ull) && (skeys[s] <= thresh);
            u32 bal = __ballot_sync(~0u, hit);
            int base = 0;
            if (lane == 0 && bal) base = atomicAdd(&sh_nsel, __popc(bal));
            base = __shfl_sync(~0u, base, 0);
            if (hit) {
                int pos = base + __popc(bal & ((1u << lane) - 1u));
                if (pos < 128) sel[pos] = s;
            }
        }
        __syncthreads();
        int nsel = sh_nsel; if (nsel > want) nsel = want;

        // rank-by-count (nsel <= 100) and emit
        if (tid < nsel) {
            int s = sel[tid];
            u64 ki = skeys[s];
            int rank = 0;
            for (int j = 0; j < nsel; j++)
                rank += (skeys[sel[j]] < ki) ? 1 : 0;
            float4 bx = g_box[b][s];
            float* bo = out + (size_t)(b * DETS + rank) * 4;
            bo[0] = bx.x; bo[1] = bx.y; bo[2] = bx.z; bo[3] = bx.w;
            out[soff + b * DETS + rank] = g_score[b][s];
            out[loff + b * DETS + rank] = (float)g_label[b][s];
        }
    }
    __syncthreads();
    if (tid == 0) g_cnt[b] = 0;   // reset for next call
}

extern "C" void kernel_launch(void* const* d_in, const int* in_sizes, int n_in,
                              void* d_out, int out_size) {
    const float* logits = (const float*)d_in[0];
    const float* reg = (const float*)d_in[1];
    const float* props = (const float*)d_in[2];
    const void* p_h = d_in[3];
    const void* p_w = d_in[4];
    float* out = (float*)d_out;

    int B = in_sizes[0] / (NPROP * NCLS);
    if (B < 1) B = 1;
    if (B > BMAX) B = BMAX;

    cudaFuncSetAttribute(k_select, cudaFuncAttributeMaxDynamicSharedMemorySize, DYN_A);
    cudaFuncSetAttribute(k_nms, cudaFuncAttributeMaxDynamicSharedMemorySize, DYN_C);

    int rows = B * NPROP;
    k_cand<<<(rows + 7) / 8, 256>>>(logits, reg, props, p_h, p_w, B);
    k_select<<<B, 1024, DYN_A>>>(reg, props, p_h, p_w, B);
    dim3 ge(NC1, B);
    k_edges<<<ge, 32>>>(B);
    k_nms<<<B, 1024, DYN_C>>>(out, B);
}

// round 16
// speedup vs baseline: 10.1668x; 1.1642x over previous
#include <cuda_runtime.h>
#include <cstdint>

typedef unsigned long long u64;
typedef unsigned int u32;

#define BMAX 8
#define NPROP 4000
#define NCLS 91
#define NC1 90
#define CAP 81920
#define SHCAP 16384
#define KPRE 2048
#define SCORE_TH 0.05f
#define NMS_TH 0.5f
#define XFORM_CLIP 4.135166556742356f
#define DETS 100
#define EDGE_CAP 8192

__device__ int g_cnt[BMAX];   // zero-init at load; reset at end of k_main
__device__ u64 g_keys[BMAX][CAP];

__device__ __forceinline__ float read_dim(const void* p) {
    int v = *(const int*)p;
    if (v > 0 && v < 1000000) return (float)v;
    return *(const float*)p;
}

// FMA-pipe exp (avoids MUFU.EX2 throughput floor). rel err ~2e-6.
__device__ __forceinline__ float fexp(float x) {
    float t = x * 1.4426950408889634f;
    t = fmaxf(t, -126.0f);
    float k = rintf(t);
    float f = t - k;
    float p = 1.3333558146e-3f;
    p = fmaf(p, f, 9.6181291077e-3f);
    p = fmaf(p, f, 5.5504108664e-2f);
    p = fmaf(p, f, 2.4022650695e-1f);
    p = fmaf(p, f, 6.9314718056e-1f);
    p = fmaf(p, f, 1.0f);
    float s = __int_as_float(((int)k + 127) << 23);
    return p * s;
}

// ---------------- k_cand: unchanged (proven) ----------------
__global__ void k_cand(const float* __restrict__ logits,
                       const float* __restrict__ reg,
                       const float* __restrict__ props,
                       const void* __restrict__ p_h,
                       const void* __restrict__ p_w,
                       int B) {
    __shared__ u64 st_keys[768];
    __shared__ int st_cnt, st_base;
    int wid = threadIdx.x >> 5, lane = threadIdx.x & 31;
    int row = blockIdx.x * 8 + wid;
    int b = row / NPROP;
    int n = row - b * NPROP;
    bool live = (row < B * NPROP);

    if (threadIdx.x == 0) st_cnt = 0;
    __syncthreads();

    if (live) {
        const float* lr = logits + (size_t)row * NCLS;
        float l0 = lr[lane];
        float l1 = lr[lane + 32];
        float l2 = (lane < NCLS - 64) ? lr[lane + 64] : -3.0e38f;

        float m = fmaxf(fmaxf(l0, l1), l2);
        #pragma unroll
        for (int o = 16; o; o >>= 1) m = fmaxf(m, __shfl_xor_sync(~0u, m, o));

        float e0 = fexp(l0 - m);
        float e1 = fexp(l1 - m);
        float e2 = (lane < NCLS - 64) ? fexp(l2 - m) : 0.0f;
        float sum = e0 + e1 + e2;
        #pragma unroll
        for (int o = 16; o; o >>= 1) sum += __shfl_xor_sync(~0u, sum, o);
        float inv = 1.0f / sum;

        float img_h = read_dim(p_h);
        float img_w = read_dim(p_w);

        float4 pr = *(const float4*)(props + (size_t)row * 4);
        float pwd = pr.z - pr.x, pht = pr.w - pr.y;
        float cx = pr.x + 0.5f * pwd, cy = pr.y + 0.5f * pht;

        #pragma unroll
        for (int slot = 0; slot < 3; slot++) {
            int p = lane + 32 * slot;
            if (p < 1 || p >= NCLS) continue;
            float e = (slot == 0) ? e0 : (slot == 1 ? e1 : e2);
            float s = e * inv;
            if (s > SCORE_TH) {
                float4 rg = *(const float4*)(reg + (size_t)row * 4 * NCLS + 4 * p);
                float dx = rg.x / 10.0f, dy = rg.y / 10.0f;
                float dw = fminf(rg.z / 5.0f, XFORM_CLIP);
                float dh = fminf(rg.w / 5.0f, XFORM_CLIP);
                float pcx = dx * pwd + cx, pcy = dy * pht + cy;
                float bw = expf(dw) * pwd, bh = expf(dh) * pht;
                float x1 = fminf(fmaxf(pcx - 0.5f * bw, 0.0f), img_w);
                float y1 = fminf(fmaxf(pcy - 0.5f * bh, 0.0f), img_h);
                float x2 = fminf(fmaxf(pcx + 0.5f * bw, 0.0f), img_w);
                float y2 = fminf(fmaxf(pcy + 0.5f * bh, 0.0f), img_h);
                if ((x2 - x1 >= 1.0f) && (y2 - y1 >= 1.0f)) {
                    u32 sb = __float_as_uint(s);
                    u32 mf = (u32)(n * NC1 + (p - 1));
                    u64 key = ((u64)(sb ^ 0xFFFFFFFFu) << 32) | (u64)mf;
                    int idx = atomicAdd(&st_cnt, 1);
                    st_keys[idx] = key;
                }
            }
        }
    }
    __syncthreads();
    int nc = st_cnt;
    if (threadIdx.x == 0 && nc > 0) st_base = atomicAdd(&g_cnt[b], nc);
    __syncthreads();
    if (nc > 0) {
        int base = st_base;
        for (int i = threadIdx.x; i < nc; i += 256)
            if (base + i < CAP) g_keys[b][base + i] = st_keys[i];
    }
}

extern __shared__ __align__(16) unsigned char dynbuf[];
#define DYN_BYTES 131072

// One block (1024 thr) per image: radix-select (unsorted), decode, class-group,
// pair-flattened smem edge gen, Jacobi NMS, rank-100 output. No global roundtrip.
__global__ void __launch_bounds__(1024, 1)
k_main(const float* __restrict__ reg,
       const float* __restrict__ props,
       const void* __restrict__ p_h,
       const void* __restrict__ p_w,
       float* __restrict__ out, int B) {
    int b = blockIdx.x;
    int tid = threadIdx.x, lane = tid & 31, wid = tid >> 5;
    const int T = 1024;

    __shared__ u64 sh_list[KPRE];          // collected keys (persist whole kernel)
    __shared__ int h[2048];
    __shared__ int warpsum[32];
    __shared__ u64 sh_prefix;
    __shared__ int sh_rem, sh_nrem, sh_bincnt, sh_binsel;
    __shared__ int sh_curcnt, sh_usebound, sh_done;
    __shared__ int sh_c2, sh_nb;
    __shared__ float sh_red[32];
    __shared__ int sh_ccnt[NCLS + 1], sh_cbase[NCLS + 1], sh_ccur[NCLS + 1];
    __shared__ u64 sh_valid[32], sh_kept[32], sh_sup[32];
    __shared__ int sh_ne, sh_changed, sh_nkept, sh_nsel;
    __shared__ int sel[128];

    u64* keys_sh = (u64*)dynbuf;                      // phase 1 only
    float4* s_obox = (float4*)dynbuf;                 // 32KB
    float*  s_area = (float*)(dynbuf + 32768);        // 8KB
    float4* s_box  = (float4*)(dynbuf + 40960);       // 32KB
    float*  s_score= (float*)(dynbuf + 73728);        // 8KB
    int*    s_label= (int*)(dynbuf + 81920);          // 8KB
    int*    cls_idx= (int*)(dynbuf + 90112);          // 8KB
    u32*    edges  = (u32*)(dynbuf + 98304);          // 32KB -> 8192 edges

    int cnt = g_cnt[b];
    if (cnt > CAP) cnt = CAP;
    bool use_sh = (cnt <= SHCAP);
    const u64* keys = use_sh ? (const u64*)keys_sh : (const u64*)g_keys[b];
    if (use_sh) {
        for (int i = tid; i < cnt; i += T) keys_sh[i] = g_keys[b][i];
    }
    __syncthreads();

    // ---- 11-bit-window radix select rank-KPRE (windows 53,42,31,20,9,0) ----
    u64 thresh = ~0ull;
    if (cnt > KPRE) {
        if (tid == 0) {
            sh_prefix = 0ull; sh_rem = KPRE; sh_curcnt = cnt;
            sh_usebound = 0; sh_done = 0;
        }
        const int shifts[6] = {53, 42, 31, 20, 9, 0};
        for (int p = 0; p < 6; p++) {
            __syncthreads();
            if (sh_done) break;
            int shift = shifts[p];
            u32 bm = (p == 5) ? 0x1FFu : 0x7FFu;
            h[tid] = 0; h[tid + 1024] = 0;
            __syncthreads();
            u64 prefix = sh_prefix;
            u64 hmask = (p == 0) ? 0ull : (~0ull << shifts[p - 1]);
            int m = sh_curcnt;
            const u64* cur = sh_usebound ? (const u64*)sh_list : keys;
            for (int i = tid; i < m; i += T) {
                u64 k = cur[i];
                if ((k & hmask) == prefix)
                    atomicAdd(&h[(int)((k >> shift) & bm)], 1);
            }
            int rem = sh_rem;
            __syncthreads();
            int a = h[2 * tid], c = h[2 * tid + 1];
            int s = a + c;
            int si = s;
            #pragma unroll
            for (int o = 1; o < 32; o <<= 1) {
                int v = __shfl_up_sync(~0u, si, o);
                if (lane >= o) si += v;
            }
            if (lane == 31) warpsum[wid] = si;
            __syncthreads();
            if (tid < 32) {
                int wv = warpsum[tid];
                #pragma unroll
                for (int o = 1; o < 32; o <<= 1) {
                    int v = __shfl_up_sync(~0u, wv, o);
                    if (tid >= o) wv += v;
                }
                warpsum[tid] = wv;
            }
            __syncthreads();
            int woff = wid ? warpsum[wid - 1] : 0;
            int incl = si + woff;
            int exclp = incl - s;
            if (exclp < rem && rem <= exclp + a) {
                sh_binsel = 2 * tid; sh_bincnt = a; sh_nrem = rem - exclp;
            } else if (exclp + a < rem && rem <= incl) {
                sh_binsel = 2 * tid + 1; sh_bincnt = c; sh_nrem = rem - exclp - a;
            }
            __syncthreads();
            int bin = sh_binsel, bc = sh_bincnt, nrem = sh_nrem;
            u64 pfull = prefix | ((u64)bin << shift);
            if (tid == 0) { sh_prefix = pfull; sh_rem = nrem; }
            if (bc == nrem) {
                if (tid == 0) {
                    sh_prefix = pfull | ((shift == 0) ? 0ull : ((1ull << shift) - 1ull));
                    sh_done = 1;
                }
            } else if (!sh_usebound && bc <= KPRE && p < 5) {
                if (tid == 0) sh_nb = 0;
                __syncthreads();
                u64 fmask = ~((1ull << shift) - 1ull);
                for (int i = tid; i < m; i += T) {
                    u64 k = cur[i];
                    if ((k & fmask) == pfull) {
                        int pos = atomicAdd(&sh_nb, 1);
                        sh_list[pos] = k;
                    }
                }
                __syncthreads();
                if (tid == 0) { sh_curcnt = bc; sh_usebound = 1; }
            }
        }
        __syncthreads();
        thresh = sh_prefix;
    }

    // ---- collect (UNSORTED), warp-aggregated ----
    if (tid == 0) sh_c2 = 0;
    __syncthreads();
    for (int i0 = 0; i0 < cnt; i0 += T) {
        int i = i0 + tid;
        bool in = (i < cnt);
        u64 k = in ? keys[i] : ~0ull;
        bool hit = in && (k <= thresh);
        u32 bal = __ballot_sync(~0u, hit);
        int base = 0;
        if (lane == 0 && bal) base = atomicAdd(&sh_c2, __popc(bal));
        base = __shfl_sync(~0u, base, 0);
        if (hit) {
            int pos = base + __popc(bal & ((1u << lane) - 1u));
            if (pos < KPRE) sh_list[pos] = k;
        }
    }
    __syncthreads();
    int ncol = sh_c2; if (ncol > KPRE) ncol = KPRE;
    for (int t = ncol + tid; t < KPRE; t += T) sh_list[t] = ~0ull;
    __syncthreads();

    // ---- decode (2 slots/thread) ----
    float img_h = read_dim(p_h);
    float img_w = read_dim(p_w);
    float lmax = 0.0f;
    float4 rbx[2];
    int rlab[2];
    #pragma unroll
    for (int q = 0; q < 2; q++) {
        int s = tid + q * 1024;
        float4 bx = make_float4(0.f, 0.f, 0.f, 0.f);
        float sc = -1.0f;
        int lab = 0;
        if (s < ncol) {
            u64 k = sh_list[s];
            u32 mf = (u32)(k & 0xFFFFFFFFu);
            sc = __uint_as_float(~((u32)(k >> 32)));
            int n = (int)(mf / NC1);
            int p = (int)(mf - (u32)n * NC1) + 1;
            int row = b * NPROP + n;
            float4 pr = *(const float4*)(props + (size_t)row * 4);
            float pwd = pr.z - pr.x, pht = pr.w - pr.y;
            float cx = pr.x + 0.5f * pwd, cy = pr.y + 0.5f * pht;
            float4 rg = *(const float4*)(reg + (size_t)row * 4 * NCLS + 4 * p);
            float dx = rg.x / 10.0f, dy = rg.y / 10.0f;
            float dw = fminf(rg.z / 5.0f, XFORM_CLIP);
            float dh = fminf(rg.w / 5.0f, XFORM_CLIP);
            float pcx = dx * pwd + cx, pcy = dy * pht + cy;
            float bw = expf(dw) * pwd, bh = expf(dh) * pht;
            bx.x = fminf(fmaxf(pcx - 0.5f * bw, 0.0f), img_w);
            bx.y = fminf(fmaxf(pcy - 0.5f * bh, 0.0f), img_h);
            bx.z = fminf(fmaxf(pcx + 0.5f * bw, 0.0f), img_w);
            bx.w = fminf(fmaxf(pcy + 0.5f * bh, 0.0f), img_h);
            lab = p;
            lmax = fmaxf(lmax, fmaxf(fmaxf(bx.x, bx.y), fmaxf(bx.z, bx.w)));
        }
        rbx[q] = bx; rlab[q] = lab;
        s_box[s] = bx;
        s_score[s] = sc;
        s_label[s] = lab;
    }
    #pragma unroll
    for (int o = 16; o; o >>= 1) lmax = fmaxf(lmax, __shfl_xor_sync(~0u, lmax, o));
    if (lane == 0) sh_red[wid] = lmax;
    __syncthreads();
    if (tid < 32) {
        float v = sh_red[tid];
        #pragma unroll
        for (int o = 16; o; o >>= 1) v = fmaxf(v, __shfl_xor_sync(~0u, v, o));
        if (tid == 0) sh_red[0] = v;
    }
    __syncthreads();
    float mc = sh_red[0];
    #pragma unroll
    for (int q = 0; q < 2; q++) {
        int s = tid + q * 1024;
        float off = (float)rlab[q] * (mc + 1.0f);
        float4 bx = rbx[q];
        float4 ob = make_float4(bx.x + off, bx.y + off, bx.z + off, bx.w + off);
        s_obox[s] = ob;
        s_area[s] = (ob.z - ob.x) * (ob.w - ob.y);
    }

    // ---- class grouping ----
    if (tid <= NCLS) { sh_ccnt[tid] = 0; }
    if (tid == 0) sh_ne = 0;
    __syncthreads();
    #pragma unroll
    for (int q = 0; q < 2; q++) {
        int s = tid + q * 1024;
        if (s < ncol) atomicAdd(&sh_ccnt[rlab[q]], 1);
    }
    __syncthreads();
    if (tid == 0) {
        int acc = 0;
        for (int c = 0; c <= NCLS; c++) { sh_cbase[c] = acc; acc += sh_ccnt[c]; }
    }
    __syncthreads();
    if (tid <= NCLS) sh_ccur[tid] = 0;
    __syncthreads();
    #pragma unroll
    for (int q = 0; q < 2; q++) {
        int s = tid + q * 1024;
        if (s < ncol) {
            int c = rlab[q];
            int pos = atomicAdd(&sh_ccur[c], 1);
            cls_idx[sh_cbase[c] + pos] = s;
        }
    }
    __syncthreads();

    // ---- pair-flattened smem edge generation (same-class pairs only) ----
    for (int c = 1 + wid; c <= NC1; c += 32) {
        int m = sh_ccnt[c];
        if (m < 2) continue;
        int base = sh_cbase[c];
        int np = m * (m - 1) / 2;
        int a = 0, off = 0, rowlen = m - 1;
        for (int p = lane; p < np; p += 32) {
            while (p - off >= rowlen) { off += rowlen; rowlen--; a++; }
            int t2 = a + 1 + (p - off);
            int u = cls_idx[base + a];
            int v = cls_idx[base + t2];
            float4 bu = s_obox[u];
            float4 bv = s_obox[v];
            float w = fminf(bu.z, bv.z) - fmaxf(bu.x, bv.x);
            float h2 = fminf(bu.w, bv.w) - fmaxf(bu.y, bv.y);
            w = fmaxf(w, 0.0f); h2 = fmaxf(h2, 0.0f);
            float inter = w * h2;
            if (inter > NMS_TH * (s_area[u] + s_area[v] - inter)) {
                u64 ku = sh_list[u], kv = sh_list[v];
                int i = (ku < kv) ? u : v;
                int j = (ku < kv) ? v : u;
                int e = atomicAdd(&sh_ne, 1);
                if (e < EDGE_CAP) edges[e] = ((u32)i << 16) | (u32)j;
            }
        }
    }

    // valid bitmask (non-pad slots)
    {
        int s0 = wid * 64 + lane;
        u32 v0 = __ballot_sync(~0u, sh_list[s0] != ~0ull);
        u32 v1 = __ballot_sync(~0u, sh_list[s0 + 32] != ~0ull);
        if (lane == 0) {
            u64 v = ((u64)v1 << 32) | (u64)v0;
            sh_valid[wid] = v;
            sh_kept[wid] = v;
        }
    }
    __syncthreads();
    int ne = sh_ne; if (ne > EDGE_CAP) ne = EDGE_CAP;

    // ---- Jacobi fixpoint == sequential greedy (forward edges by key) ----
    for (int it = 0; it < 64; it++) {
        if (tid < 32) sh_sup[tid] = 0ull;
        if (tid == 0) sh_changed = 0;
        __syncthreads();
        for (int e = tid; e < ne; e += T) {
            u32 pk = edges[e];
            int i = pk >> 16, j = pk & 0xFFFF;
            if ((sh_kept[i >> 6] >> (i & 63)) & 1ull)
                atomicOr(&sh_sup[j >> 6], 1ull << (j & 63));
        }
        __syncthreads();
        if (tid < 32) {
            u64 nk = sh_valid[tid] & ~sh_sup[tid];
            if (nk != sh_kept[tid]) { sh_kept[tid] = nk; sh_changed = 1; }
        }
        __syncthreads();
        if (!sh_changed) break;
    }

    // count kept
    if (tid < 32) {
        int c = __popcll(sh_kept[tid]);
        #pragma unroll
        for (int o = 16; o; o >>= 1) c += __shfl_xor_sync(~0u, c, o);
        if (tid == 0) sh_nkept = c;
    }
    __syncthreads();
    int nkept = sh_nkept;
    int want = nkept < DETS ? nkept : DETS;

    // ---- defaults ----
    const int soff = B * DETS * 4;
    const int loff = B * DETS * 4 + B * DETS;
    for (int i = tid; i < DETS; i += T) {
        float* bo = out + (size_t)(b * DETS + i) * 4;
        bo[0] = 0.f; bo[1] = 0.f; bo[2] = 0.f; bo[3] = 0.f;
        out[soff + b * DETS + i] = 0.f;
        out[loff + b * DETS + i] = -1.f;
    }

    if (want > 0) {
        // radix-select rank-want key among KEPT keys (typically 1 pass)
        u64 thr2 = ~0ull;
        if (nkept > want) {
            if (tid == 0) { sh_prefix = 0ull; sh_rem = want; sh_done = 0; }
            const int shifts[6] = {53, 42, 31, 20, 9, 0};
            for (int p = 0; p < 6; p++) {
                __syncthreads();
                if (sh_done) break;
                int shift = shifts[p];
                u32 bm = (p == 5) ? 0x1FFu : 0x7FFu;
                h[tid] = 0; h[tid + 1024] = 0;
                __syncthreads();
                u64 prefix = sh_prefix;
                u64 hmask = (p == 0) ? 0ull : (~0ull << shifts[p - 1]);
                #pragma unroll
                for (int q = 0; q < 2; q++) {
                    int s = tid + q * 1024;
                    if ((sh_kept[s >> 6] >> (s & 63)) & 1ull) {
                        u64 k = sh_list[s];
                        if ((k & hmask) == prefix)
                            atomicAdd(&h[(int)((k >> shift) & bm)], 1);
                    }
                }
                int rem = sh_rem;
                __syncthreads();
                int a = h[2 * tid], c = h[2 * tid + 1];
                int s2 = a + c;
                int si = s2;
                #pragma unroll
                for (int o = 1; o < 32; o <<= 1) {
                    int v = __shfl_up_sync(~0u, si, o);
                    if (lane >= o) si += v;
                }
                if (lane == 31) warpsum[wid] = si;
                __syncthreads();
                if (tid < 32) {
                    int wv = warpsum[tid];
                    #pragma unroll
                    for (int o = 1; o < 32; o <<= 1) {
                        int v = __shfl_up_sync(~0u, wv, o);
                        if (tid >= o) wv += v;
                    }
                    warpsum[tid] = wv;
                }
                __syncthreads();
                int woff = wid ? warpsum[wid - 1] : 0;
                int incl = si + woff;
                int exclp = incl - s2;
                if (exclp < rem && rem <= exclp + a) {
                    sh_binsel = 2 * tid; sh_bincnt = a; sh_nrem = rem - exclp;
                } else if (exclp + a < rem && rem <= incl) {
                    sh_binsel = 2 * tid + 1; sh_bincnt = c; sh_nrem = rem - exclp - a;
                }
                __syncthreads();
                int bin = sh_binsel, bc = sh_bincnt, nrem = sh_nrem;
                u64 pfull = prefix | ((u64)bin << shift);
                if (tid == 0) { sh_prefix = pfull; sh_rem = nrem; }
                if (bc == nrem) {
                    if (tid == 0) {
                        sh_prefix = pfull | ((shift == 0) ? 0ull : ((1ull << shift) - 1ull));
                        sh_done = 1;
                    }
                }
            }
            __syncthreads();
            thr2 = sh_prefix;
        }

        // collect kept keys <= thr2 (exactly `want`)
        if (tid == 0) sh_nsel = 0;
        __syncthreads();
        #pragma unroll
        for (int q = 0; q < 2; q++) {
            int s = tid + q * 1024;
            bool hit = ((sh_kept[s >> 6] >> (s & 63)) & 1ull) && (sh_list[s] <= thr2);
            u32 bal = __ballot_sync(~0u, hit);
            int base = 0;
            if (lane == 0 && bal) base = atomicAdd(&sh_nsel, __popc(bal));
            base = __shfl_sync(~0u, base, 0);
            if (hit) {
                int pos = base + __popc(bal & ((1u << lane) - 1u));
                if (pos < 128) sel[pos] = s;
            }
        }
        __syncthreads();
        int nsel = sh_nsel; if (nsel > want) nsel = want;

        // rank-by-count (nsel <= 100) and emit
        if (tid < nsel) {
            int s = sel[tid];
            u64 ki = sh_list[s];
            int rank = 0;
            for (int j = 0; j < nsel; j++)
                rank += (sh_list[sel[j]] < ki) ? 1 : 0;
            float4 bx = s_box[s];
            float* bo = out + (size_t)(b * DETS + rank) * 4;
            bo[0] = bx.x; bo[1] = bx.y; bo[2] = bx.z; bo[3] = bx.w;
            out[soff + b * DETS + rank] = s_score[s];
            out[loff + b * DETS + rank] = (float)s_label[s];
        }
    }
    __syncthreads();
    if (tid == 0) g_cnt[b] = 0;   // reset for next call
}

extern "C" void kernel_launch(void* const* d_in, const int* in_sizes, int n_in,
                              void* d_out, int out_size) {
    const float* logits = (const float*)d_in[0];
    const float* reg = (const float*)d_in[1];
    const float* props = (const float*)d_in[2];
    const void* p_h = d_in[3];
    const void* p_w = d_in[4];
    float* out = (float*)d_out;

    int B = in_sizes[0] / (NPROP * NCLS);
    if (B < 1) B = 1;
    if (B > BMAX) B = BMAX;

    cudaFuncSetAttribute(k_main, cudaFuncAttributeMaxDynamicSharedMemorySize, DYN_BYTES);

    int rows = B * NPROP;
    k_cand<<<(rows + 7) / 8, 256>>>(logits, reg, props, p_h, p_w, B);
    k_main<<<B, 1024, DYN_BYTES>>>(reg, props, p_h, p_w, out, B);
}